// round 14
// baseline (speedup 1.0000x reference)
#include <cuda_runtime.h>
#include <cuda_fp16.h>
#include <stdint.h>

#define N_NODES 100000
#define N_EDGES 1600000
#define IN_F 50
#define HID 256
#define OUT_F 121
#define M_TILES ((N_NODES + 127) / 128)   // 782

// ===================== scratch (static __device__) ==========================
__device__ int   g_flag;
__device__ int   g_total;
__device__ int   g_deg[N_NODES];
__device__ int   g_beg[N_NODES];
__device__ float g_dinv[N_NODES];
__device__ int   g_cur[N_NODES];
__device__ int   g_csr[N_EDGES];

__device__ __half g_W1[256 * 64];     // W1^T padded K->64  [n][k]
__device__ __half g_W2[256 * 256];    // W2^T
__device__ __half g_W3[128 * 256];    // W3^T padded N->128

__device__ __half g_A1[(size_t)N_NODES * 64];    // agg1 out (GEMM1 A)
__device__ __half g_A2[(size_t)N_NODES * 256];   // agg2 out (GEMM2 A)
__device__ __half g_A3[(size_t)N_NODES * 256];   // relu(GEMM2 out) (GEMM3 A)
__device__ __half g_h1h[(size_t)N_NODES * 256];  // h1 fp16 (51.2MB: L2-resident)
__device__ __half g_t3h[(size_t)N_NODES * 128];  // t3 fp16 (25.6MB: L2-resident)

// ===================== small PTX helpers (baseline features only) ===========
__device__ __forceinline__ uint32_t smem_u32(const void* p) {
    uint32_t a;
    asm("{ .reg .u64 t; cvta.to.shared.u64 t, %1; cvt.u32.u64 %0, t; }" : "=r"(a) : "l"(p));
    return a;
}

#define CP_ASYNC16(dst_u32, src_ptr) \
    asm volatile("cp.async.cg.shared.global [%0], [%1], 16;" :: "r"(dst_u32), "l"(src_ptr))
#define CP_COMMIT() asm volatile("cp.async.commit_group;" ::: "memory")

#define LDM_X4(R, ADDR) \
    asm volatile("ldmatrix.sync.aligned.m8n8.x4.shared.b16 {%0,%1,%2,%3}, [%4];" \
        : "=r"((R)[0]), "=r"((R)[1]), "=r"((R)[2]), "=r"((R)[3]) : "r"(ADDR))

__device__ __forceinline__ void mma16816h(float* d, const uint32_t* a, const uint32_t* b) {
    asm volatile(
        "mma.sync.aligned.m16n8k16.row.col.f32.f16.f16.f32 "
        "{%0,%1,%2,%3}, {%4,%5,%6,%7}, {%8,%9}, {%0,%1,%2,%3};"
        : "+f"(d[0]), "+f"(d[1]), "+f"(d[2]), "+f"(d[3])
        : "r"(a[0]), "r"(a[1]), "r"(a[2]), "r"(a[3]), "r"(b[0]), "r"(b[1]));
}

// ===================== helpers: load 8 edge indices =========================
__device__ __forceinline__ void load8(const void* ei, size_t elem_off, int e8,
                                      int* v) {
    if (g_flag) {
        const int4* p = (const int4*)((const int*)ei + elem_off);
        int4 a = p[e8 * 2], b = p[e8 * 2 + 1];
        v[0] = a.x; v[1] = a.y; v[2] = a.z; v[3] = a.w;
        v[4] = b.x; v[5] = b.y; v[6] = b.z; v[7] = b.w;
    } else {
        const longlong2* p = (const longlong2*)((const long long*)ei + elem_off);
        #pragma unroll
        for (int q = 0; q < 4; q++) {
            longlong2 a = p[e8 * 4 + q];
            v[q * 2] = (int)a.x; v[q * 2 + 1] = (int)a.y;
        }
    }
}

// ===================== kernel 1: detect (block 0) + init (all blocks) =======
__global__ void k_front(const long long* __restrict__ ei64) {
    int v = blockIdx.x * blockDim.x + threadIdx.x;
    if (v < N_NODES) g_deg[v] = 1;
    if (blockIdx.x == 0) {
        __shared__ int bad;
        if (threadIdx.x == 0) { bad = 0; g_total = 0; }
        __syncthreads();
        int ok = 1;
        for (int i = threadIdx.x; i < 4096; i += 256) {
            long long t = ei64[i];
            if (t < 0 || t >= N_NODES) ok = 0;
        }
        if (!ok) atomicOr(&bad, 1);
        __syncthreads();
        if (threadIdx.x == 0) g_flag = bad;
    }
}

// ===================== kernel 2: degcount (8 edges/thr) || prepw ============
#define NB_CONV ((N_EDGES / 8 + 255) / 256)            // 782
#define NB_PW   ((256*64 + 256*256 + 128*256 + 255) / 256)  // 480

__global__ void k_mid(const void* __restrict__ ei,
                      const float* __restrict__ W1, const float* __restrict__ W2,
                      const float* __restrict__ W3) {
    int b = blockIdx.x;
    if (b < NB_CONV) {
        int e8 = b * 256 + threadIdx.x;
        if (e8 * 8 >= N_EDGES) return;
        int c[8];
        load8(ei, N_EDGES, e8, c);
        #pragma unroll
        for (int q = 0; q < 8; q++) atomicAdd(&g_deg[c[q]], 1);
    } else {
        // ---- weight prep fp16 transposed/padded ----
        int i = (b - NB_CONV) * 256 + threadIdx.x;
        if (i < 256 * 64) {
            int n = i >> 6, k = i & 63;
            g_W1[i] = __float2half((k < IN_F) ? W1[(size_t)k * 256 + n] : 0.f);
        } else if (i < 256 * 64 + 256 * 256) {
            int j = i - 256 * 64;
            int n = j >> 8, k = j & 255;
            g_W2[j] = __float2half(W2[(size_t)k * 256 + n]);
        } else if (i < 256 * 64 + 256 * 256 + 128 * 256) {
            int j = i - 256 * 64 - 256 * 256;
            int n = j >> 8, k = j & 255;
            g_W3[j] = __float2half((n < OUT_F) ? W3[(size_t)k * OUT_F + n] : 0.f);
        }
    }
}

// ===================== CSR range allocation (no scan): warp-agg atomic ======
__global__ void k_alloc() {
    int v = blockIdx.x * blockDim.x + threadIdx.x;
    int lane = threadIdx.x & 31;
    int d = (v < N_NODES) ? g_deg[v] : 1;
    if (v < N_NODES) g_dinv[v] = rsqrtf((float)d);
    int cnt = (v < N_NODES) ? (d - 1) : 0;
    int pre = cnt;
    #pragma unroll
    for (int o = 1; o < 32; o <<= 1) {
        int t = __shfl_up_sync(0xFFFFFFFFu, pre, o);
        if (lane >= o) pre += t;
    }
    int total = __shfl_sync(0xFFFFFFFFu, pre, 31);
    int base = 0;
    if (lane == 31 && total > 0) base = atomicAdd(&g_total, total);
    base = __shfl_sync(0xFFFFFFFFu, base, 31);
    if (v < N_NODES) {
        int beg = base + pre - cnt;
        g_beg[v] = beg;
        g_cur[v] = beg;
    }
}

// ===================== scatter: 8 edges/thread, MLP=8 =======================
__global__ void k_scatter(const void* __restrict__ ei) {
    int e8 = blockIdx.x * blockDim.x + threadIdx.x;
    if (e8 * 8 >= N_EDGES) return;
    int r[8], c[8];
    load8(ei, 0, e8, r);
    load8(ei, N_EDGES, e8, c);
    int p[8];
    #pragma unroll
    for (int q = 0; q < 8; q++) p[q] = atomicAdd(&g_cur[c[q]], 1);
    #pragma unroll
    for (int q = 0; q < 8; q++) g_csr[p[q]] = r[q];
}

// ===================== aggregation ==========================================
// layer-1 agg: x fp32 [N][50] (float2 lanes, row stride 25), out fp16 [N][64]
__global__ void k_agg1(const float2* __restrict__ X2) {
    int gw = (blockIdx.x * blockDim.x + threadIdx.x) >> 5;
    int lane = threadIdx.x & 31;
    if (gw >= N_NODES) return;
    int node = gw;
    bool act = lane < 25;
    int c2 = act ? lane : 0;
    float dv = g_dinv[node];
    float2 xv = X2[(size_t)node * 25 + c2];
    float ax = dv * xv.x, ay = dv * xv.y;
    int beg = g_beg[node], end = beg + g_deg[node] - 1;
    int j = beg;
    for (; j + 4 <= end; j += 4) {
        int u0 = g_csr[j], u1 = g_csr[j + 1], u2 = g_csr[j + 2], u3 = g_csr[j + 3];
        float d0 = g_dinv[u0], d1 = g_dinv[u1], d2 = g_dinv[u2], d3 = g_dinv[u3];
        float2 a0 = X2[(size_t)u0 * 25 + c2];
        float2 a1 = X2[(size_t)u1 * 25 + c2];
        float2 a2 = X2[(size_t)u2 * 25 + c2];
        float2 a3 = X2[(size_t)u3 * 25 + c2];
        ax += d0 * a0.x; ay += d0 * a0.y;
        ax += d1 * a1.x; ay += d1 * a1.y;
        ax += d2 * a2.x; ay += d2 * a2.y;
        ax += d3 * a3.x; ay += d3 * a3.y;
    }
    for (; j < end; j++) {
        int u = g_csr[j];
        float d = g_dinv[u];
        float2 a = X2[(size_t)u * 25 + c2];
        ax += d * a.x; ay += d * a.y;
    }
    float v0 = act ? dv * ax : 0.f;
    float v1 = act ? dv * ay : 0.f;
    *(__half2*)(g_A1 + (size_t)node * 64 + lane * 2) = __floats2half2_rn(v0, v1);
}

// layer-2 agg: single pass, uint4 lanes (8 halves), 32 lanes cover 256 cols.
__global__ void k_agg2() {
    const uint4* X = (const uint4*)g_h1h;       // row stride 32 uint4
    int gw = (blockIdx.x * blockDim.x + threadIdx.x) >> 5;
    int lane = threadIdx.x & 31;
    if (gw >= N_NODES) return;
    int node = gw;
    float dv = g_dinv[node];
    float a[8];
    {
        uint4 raw = X[(size_t)node * 32 + lane];
        float2 f0 = __half22float2(*(__half2*)&raw.x);
        float2 f1 = __half22float2(*(__half2*)&raw.y);
        float2 f2 = __half22float2(*(__half2*)&raw.z);
        float2 f3 = __half22float2(*(__half2*)&raw.w);
        a[0] = dv * f0.x; a[1] = dv * f0.y; a[2] = dv * f1.x; a[3] = dv * f1.y;
        a[4] = dv * f2.x; a[5] = dv * f2.y; a[6] = dv * f3.x; a[7] = dv * f3.y;
    }
    int beg = g_beg[node], end = beg + g_deg[node] - 1;
    int j = beg;
    for (; j + 4 <= end; j += 4) {
        int u0 = g_csr[j], u1 = g_csr[j + 1], u2 = g_csr[j + 2], u3 = g_csr[j + 3];
        float d0 = g_dinv[u0], d1 = g_dinv[u1], d2 = g_dinv[u2], d3 = g_dinv[u3];
        uint4 r0 = X[(size_t)u0 * 32 + lane];
        uint4 r1 = X[(size_t)u1 * 32 + lane];
        uint4 r2 = X[(size_t)u2 * 32 + lane];
        uint4 r3 = X[(size_t)u3 * 32 + lane];
        {
            float2 f0 = __half22float2(*(__half2*)&r0.x), f1 = __half22float2(*(__half2*)&r0.y);
            float2 f2 = __half22float2(*(__half2*)&r0.z), f3 = __half22float2(*(__half2*)&r0.w);
            a[0] += d0 * f0.x; a[1] += d0 * f0.y; a[2] += d0 * f1.x; a[3] += d0 * f1.y;
            a[4] += d0 * f2.x; a[5] += d0 * f2.y; a[6] += d0 * f3.x; a[7] += d0 * f3.y;
        }
        {
            float2 f0 = __half22float2(*(__half2*)&r1.x), f1 = __half22float2(*(__half2*)&r1.y);
            float2 f2 = __half22float2(*(__half2*)&r1.z), f3 = __half22float2(*(__half2*)&r1.w);
            a[0] += d1 * f0.x; a[1] += d1 * f0.y; a[2] += d1 * f1.x; a[3] += d1 * f1.y;
            a[4] += d1 * f2.x; a[5] += d1 * f2.y; a[6] += d1 * f3.x; a[7] += d1 * f3.y;
        }
        {
            float2 f0 = __half22float2(*(__half2*)&r2.x), f1 = __half22float2(*(__half2*)&r2.y);
            float2 f2 = __half22float2(*(__half2*)&r2.z), f3 = __half22float2(*(__half2*)&r2.w);
            a[0] += d2 * f0.x; a[1] += d2 * f0.y; a[2] += d2 * f1.x; a[3] += d2 * f1.y;
            a[4] += d2 * f2.x; a[5] += d2 * f2.y; a[6] += d2 * f3.x; a[7] += d2 * f3.y;
        }
        {
            float2 f0 = __half22float2(*(__half2*)&r3.x), f1 = __half22float2(*(__half2*)&r3.y);
            float2 f2 = __half22float2(*(__half2*)&r3.z), f3 = __half22float2(*(__half2*)&r3.w);
            a[0] += d3 * f0.x; a[1] += d3 * f0.y; a[2] += d3 * f1.x; a[3] += d3 * f1.y;
            a[4] += d3 * f2.x; a[5] += d3 * f2.y; a[6] += d3 * f3.x; a[7] += d3 * f3.y;
        }
    }
    for (; j < end; j++) {
        int u = g_csr[j];
        float d = g_dinv[u];
        uint4 r = X[(size_t)u * 32 + lane];
        float2 f0 = __half22float2(*(__half2*)&r.x), f1 = __half22float2(*(__half2*)&r.y);
        float2 f2 = __half22float2(*(__half2*)&r.z), f3 = __half22float2(*(__half2*)&r.w);
        a[0] += d * f0.x; a[1] += d * f0.y; a[2] += d * f1.x; a[3] += d * f1.y;
        a[4] += d * f2.x; a[5] += d * f2.y; a[6] += d * f3.x; a[7] += d * f3.y;
    }
    uint4 outv;
    *(__half2*)&outv.x = __floats2half2_rn(a[0] * dv, a[1] * dv);
    *(__half2*)&outv.y = __floats2half2_rn(a[2] * dv, a[3] * dv);
    *(__half2*)&outv.z = __floats2half2_rn(a[4] * dv, a[5] * dv);
    *(__half2*)&outv.w = __floats2half2_rn(a[6] * dv, a[7] * dv);
    *(uint4*)(g_A2 + (size_t)node * 256 + lane * 8) = outv;
}

// final agg: t3 fp16 [N][128] (uint2 lanes), +bias, out [N][121] fp32
__global__ void k_agg_out(float* __restrict__ OUT, const float* __restrict__ bias) {
    const uint2* X4 = (const uint2*)g_t3h;      // row stride 32 uint2
    int gw = (blockIdx.x * blockDim.x + threadIdx.x) >> 5;
    int lane = threadIdx.x & 31;
    if (gw >= N_NODES) return;
    int node = gw;
    float dv = g_dinv[node];
    uint2 raw = X4[(size_t)node * 32 + lane];
    float2 f01 = __half22float2(*(__half2*)&raw.x);
    float2 f23 = __half22float2(*(__half2*)&raw.y);
    float a0 = dv * f01.x, a1 = dv * f01.y, a2 = dv * f23.x, a3 = dv * f23.y;
    int beg = g_beg[node], end = beg + g_deg[node] - 1;
    int j = beg;
    for (; j + 4 <= end; j += 4) {
        int u0 = g_csr[j], u1 = g_csr[j + 1], u2 = g_csr[j + 2], u3 = g_csr[j + 3];
        float d0 = g_dinv[u0], d1 = g_dinv[u1], d2 = g_dinv[u2], d3 = g_dinv[u3];
        uint2 r0 = X4[(size_t)u0 * 32 + lane];
        uint2 r1 = X4[(size_t)u1 * 32 + lane];
        uint2 r2 = X4[(size_t)u2 * 32 + lane];
        uint2 r3 = X4[(size_t)u3 * 32 + lane];
        float2 p0a = __half22float2(*(__half2*)&r0.x), p0b = __half22float2(*(__half2*)&r0.y);
        float2 p1a = __half22float2(*(__half2*)&r1.x), p1b = __half22float2(*(__half2*)&r1.y);
        float2 p2a = __half22float2(*(__half2*)&r2.x), p2b = __half22float2(*(__half2*)&r2.y);
        float2 p3a = __half22float2(*(__half2*)&r3.x), p3b = __half22float2(*(__half2*)&r3.y);
        a0 += d0 * p0a.x; a1 += d0 * p0a.y; a2 += d0 * p0b.x; a3 += d0 * p0b.y;
        a0 += d1 * p1a.x; a1 += d1 * p1a.y; a2 += d1 * p1b.x; a3 += d1 * p1b.y;
        a0 += d2 * p2a.x; a1 += d2 * p2a.y; a2 += d2 * p2b.x; a3 += d2 * p2b.y;
        a0 += d3 * p3a.x; a1 += d3 * p3a.y; a2 += d3 * p3b.x; a3 += d3 * p3b.y;
    }
    for (; j < end; j++) {
        int u = g_csr[j];
        float d = g_dinv[u];
        uint2 r = X4[(size_t)u * 32 + lane];
        float2 pa = __half22float2(*(__half2*)&r.x), pb = __half22float2(*(__half2*)&r.y);
        a0 += d * pa.x; a1 += d * pa.y; a2 += d * pb.x; a3 += d * pb.y;
    }
    int c = lane * 4;
    float* dst = OUT + (size_t)node * OUT_F;
    if (c + 0 < OUT_F) dst[c + 0] = dv * a0 + bias[c + 0];
    if (c + 1 < OUT_F) dst[c + 1] = dv * a1 + bias[c + 1];
    if (c + 2 < OUT_F) dst[c + 2] = dv * a2 + bias[c + 2];
    if (c + 3 < OUT_F) dst[c + 3] = dv * a3 + bias[c + 3];
}

// ===================== warp-MMA GEMM (fp16, BK=64, 2-stage cp.async) ========
template<int KT, int NNTOT, bool BIAS, bool RELU>
__global__ void __launch_bounds__(256, 2)
k_mma(const __half* __restrict__ A, const __half* __restrict__ B,
      const float* __restrict__ bias, __half* __restrict__ C) {
    constexpr int ASTR = KT * 64;
    constexpr int PAD = 72;                  // 64 + 8 halves (conflict-free)
    constexpr int ST = 128 * PAD;            // elements per array per stage
    extern __shared__ __half dsm[];

    const int tid = threadIdx.x;
    const int wid = tid >> 5, lane = tid & 31;
    const int wm = wid & 3, wn = wid >> 2;
    const int m0 = blockIdx.x * 128;
    const int n0 = blockIdx.y * 128;

    float acc[2][8][4];
    #pragma unroll
    for (int mt = 0; mt < 2; mt++)
        #pragma unroll
        for (int nt = 0; nt < 8; nt++)
            #pragma unroll
            for (int q = 0; q < 4; q++) acc[mt][nt][q] = 0.f;

    auto stage = [&](int s, int c) {
        __half* base = dsm + s * 2 * ST;
        #pragma unroll
        for (int it = 0; it < 4; it++) {
            int idx = it * 256 + tid;        // 0..1023: row=idx>>3, chk=idx&7
            int row = idx >> 3, chk = idx & 7;
            int m = m0 + row; if (m >= N_NODES) m = N_NODES - 1;
            size_t goA = (size_t)m * ASTR + c * 64 + chk * 8;
            size_t goB = (size_t)(n0 + row) * ASTR + c * 64 + chk * 8;
            int so = row * PAD + chk * 8;
            CP_ASYNC16(smem_u32(base + so), A + goA);
            CP_ASYNC16(smem_u32(base + ST + so), B + goB);
        }
        CP_COMMIT();
    };

    stage(0, 0);
    for (int c = 0; c < KT; c++) {
        if (c + 1 < KT) {
            stage((c + 1) & 1, c + 1);
            asm volatile("cp.async.wait_group 1;" ::: "memory");
        } else {
            asm volatile("cp.async.wait_group 0;" ::: "memory");
        }
        __syncthreads();

        const __half* sA = dsm + (c & 1) * 2 * ST;
        const __half* sB = sA + ST;

        #pragma unroll
        for (int ks = 0; ks < 4; ks++) {
            const int kc = ks * 16;
            uint32_t a_f[2][4];
            #pragma unroll
            for (int mt = 0; mt < 2; mt++) {
                int r = wm * 32 + mt * 16 + (lane & 15);
                int cA = kc + ((lane >> 4) << 3);
                LDM_X4(a_f[mt], smem_u32(sA + r * PAD + cA));
            }
            #pragma unroll
            for (int ntp = 0; ntp < 4; ntp++) {
                int br = wn * 64 + ntp * 16 + (lane & 7) + ((lane & 16) ? 8 : 0);
                int cB = kc + ((lane & 8) ? 8 : 0);
                uint32_t b_f[4];
                LDM_X4(b_f, smem_u32(sB + br * PAD + cB));
                #pragma unroll
                for (int half = 0; half < 2; half++) {
                    int nt = ntp * 2 + half;
                    #pragma unroll
                    for (int mt = 0; mt < 2; mt++)
                        mma16816h(acc[mt][nt], a_f[mt], b_f + 2 * half);
                }
            }
        }
        __syncthreads();
    }

    #pragma unroll
    for (int mt = 0; mt < 2; mt++) {
        int mrow = m0 + wm * 32 + mt * 16 + (lane >> 2);
        #pragma unroll
        for (int nt = 0; nt < 8; nt++) {
            int n = n0 + wn * 64 + nt * 8 + (lane & 3) * 2;
            float v0 = acc[mt][nt][0], v1 = acc[mt][nt][1];
            float v2 = acc[mt][nt][2], v3 = acc[mt][nt][3];
            if (BIAS) {
                float bb0 = bias[n], bb1 = bias[n + 1];
                v0 += bb0; v1 += bb1; v2 += bb0; v3 += bb1;
            }
            if (RELU) {
                v0 = fmaxf(v0, 0.f); v1 = fmaxf(v1, 0.f);
                v2 = fmaxf(v2, 0.f); v3 = fmaxf(v3, 0.f);
            }
            if (mrow < N_NODES)
                *(__half2*)(C + (size_t)mrow * NNTOT + n) = __floats2half2_rn(v0, v1);
            if (mrow + 8 < N_NODES)
                *(__half2*)(C + (size_t)(mrow + 8) * NNTOT + n) = __floats2half2_rn(v2, v3);
        }
    }
}

// ===================== launch ===============================================
static inline void* sym(const void* s) {
    void* p = nullptr;
    cudaGetSymbolAddress(&p, s);
    return p;
}

extern "C" void kernel_launch(void* const* d_in, const int* in_sizes, int n_in,
                              void* d_out, int out_size) {
    const float* x   = (const float*)d_in[0];
    const void*  ei  = d_in[1];
    const float* W1  = (const float*)d_in[2];
    const float* b1  = (const float*)d_in[3];
    const float* W2  = (const float*)d_in[4];
    const float* b2  = (const float*)d_in[5];
    const float* W3  = (const float*)d_in[6];
    const float* b3  = (const float*)d_in[7];
    float*       out = (float*)d_out;

    __half* pW1 = (__half*)sym(g_W1);
    __half* pW2 = (__half*)sym(g_W2);
    __half* pW3 = (__half*)sym(g_W3);
    __half* A1  = (__half*)sym(g_A1);
    __half* A2  = (__half*)sym(g_A2);
    __half* A3  = (__half*)sym(g_A3);
    __half* h1h = (__half*)sym(g_h1h);
    __half* t3h = (__half*)sym(g_t3h);

    const int NB_N = (N_NODES + 255) / 256;

    const int SMEM_MMA = 2 * 2 * 128 * 72 * (int)sizeof(__half);  // 73728
    cudaFuncSetAttribute(k_mma<1, 256, true,  true >, cudaFuncAttributeMaxDynamicSharedMemorySize, SMEM_MMA);
    cudaFuncSetAttribute(k_mma<4, 256, true,  true >, cudaFuncAttributeMaxDynamicSharedMemorySize, SMEM_MMA);
    cudaFuncSetAttribute(k_mma<4, 128, false, false>, cudaFuncAttributeMaxDynamicSharedMemorySize, SMEM_MMA);

    // preprocessing: detect+init -> (degcount||prepw) -> alloc -> scatter
    k_front  <<<NB_N, 256>>>((const long long*)ei);
    k_mid    <<<NB_CONV + NB_PW, 256>>>(ei, W1, W2, W3);
    k_alloc  <<<NB_N, 256>>>();
    k_scatter<<<(N_EDGES / 8 + 255) / 256, 256>>>(ei);

    // Layer 1: agg(x fp32) -> A1; GEMM K=64 -> h1 fp16 (+b1, relu)
    k_agg1<<<(N_NODES * 32 + 255) / 256, 256>>>((const float2*)x);
    {
        dim3 grid(M_TILES, 2);
        k_mma<1, 256, true, true><<<grid, 256, SMEM_MMA>>>(A1, pW1, b1, h1h);
    }

    // Layer 2: agg(h1) single-pass -> A2; GEMM K=256 -> A3 fp16 (+b2, relu)
    k_agg2<<<(N_NODES * 32 + 255) / 256, 256>>>();
    {
        dim3 grid(M_TILES, 2);
        k_mma<4, 256, true, true><<<grid, 256, SMEM_MMA>>>(A2, pW2, b2, A3);
    }

    // Layer 3: GEMM K=256 -> t3 fp16; agg(t3)+b3 -> out fp32
    {
        dim3 grid(M_TILES, 1);
        k_mma<4, 128, false, false><<<grid, 256, SMEM_MMA>>>(A3, pW3, nullptr, t3h);
    }
    k_agg_out<<<(N_NODES * 32 + 255) / 256, 256>>>(out, b3);
}

// round 15
// speedup vs baseline: 1.0188x; 1.0188x over previous
#include <cuda_runtime.h>
#include <cuda_fp16.h>
#include <stdint.h>

#define N_NODES 100000
#define N_EDGES 1600000
#define IN_F 50
#define HID 256
#define OUT_F 121
#define M_TILES ((N_NODES + 127) / 128)   // 782

// ===================== scratch (static __device__) ==========================
__device__ int   g_flag;
__device__ int   g_total;
__device__ int   g_deg[N_NODES];
__device__ int   g_beg[N_NODES];
__device__ float g_dinv[N_NODES];
__device__ int   g_cur[N_NODES];
__device__ int   g_csr[N_EDGES];

__device__ __half g_W1[256 * 64];     // W1^T padded K->64  [n][k]
__device__ __half g_W2[256 * 256];    // W2^T
__device__ __half g_W3[128 * 256];    // W3^T padded N->128

__device__ __half g_A1[(size_t)N_NODES * 64];    // agg1 out (GEMM1 A)
__device__ __half g_A2[(size_t)N_NODES * 256];   // agg2 out (GEMM2 A)
__device__ __half g_A3[(size_t)N_NODES * 256];   // relu(GEMM2 out) (GEMM3 A)
__device__ __half g_xh [(size_t)N_NODES * 52];   // x fp16, padded 50->52
__device__ __half g_h1h[(size_t)N_NODES * 256];  // h1 fp16 (51.2MB: L2-resident)
__device__ __half g_t3h[(size_t)N_NODES * 128];  // t3 fp16 (25.6MB: L2-resident)

// ===================== small PTX helpers (baseline features only) ===========
__device__ __forceinline__ uint32_t smem_u32(const void* p) {
    uint32_t a;
    asm("{ .reg .u64 t; cvta.to.shared.u64 t, %1; cvt.u32.u64 %0, t; }" : "=r"(a) : "l"(p));
    return a;
}

#define CP_ASYNC16(dst_u32, src_ptr) \
    asm volatile("cp.async.cg.shared.global [%0], [%1], 16;" :: "r"(dst_u32), "l"(src_ptr))
#define CP_COMMIT() asm volatile("cp.async.commit_group;" ::: "memory")

#define LDM_X4(R, ADDR) \
    asm volatile("ldmatrix.sync.aligned.m8n8.x4.shared.b16 {%0,%1,%2,%3}, [%4];" \
        : "=r"((R)[0]), "=r"((R)[1]), "=r"((R)[2]), "=r"((R)[3]) : "r"(ADDR))

__device__ __forceinline__ void mma16816h(float* d, const uint32_t* a, const uint32_t* b) {
    asm volatile(
        "mma.sync.aligned.m16n8k16.row.col.f32.f16.f16.f32 "
        "{%0,%1,%2,%3}, {%4,%5,%6,%7}, {%8,%9}, {%0,%1,%2,%3};"
        : "+f"(d[0]), "+f"(d[1]), "+f"(d[2]), "+f"(d[3])
        : "r"(a[0]), "r"(a[1]), "r"(a[2]), "r"(a[3]), "r"(b[0]), "r"(b[1]));
}

// ===================== helpers: load 4 edge indices =========================
__device__ __forceinline__ void load4(const void* ei, size_t elem_off, int e4,
                                      int* v) {
    if (g_flag) {
        int4 a = ((const int4*)((const int*)ei + elem_off))[e4];
        v[0] = a.x; v[1] = a.y; v[2] = a.z; v[3] = a.w;
    } else {
        const longlong2* p = (const longlong2*)((const long long*)ei + elem_off);
        longlong2 a = p[e4 * 2], b = p[e4 * 2 + 1];
        v[0] = (int)a.x; v[1] = (int)a.y; v[2] = (int)b.x; v[3] = (int)b.y;
    }
}

// ===================== kernel 1: detect (block 0) + init (all blocks) =======
__global__ void k_front(const long long* __restrict__ ei64) {
    int v = blockIdx.x * blockDim.x + threadIdx.x;
    if (v < N_NODES) g_deg[v] = 1;
    if (blockIdx.x == 0) {
        __shared__ int bad;
        if (threadIdx.x == 0) { bad = 0; g_total = 0; }
        __syncthreads();
        int ok = 1;
        for (int i = threadIdx.x; i < 4096; i += 256) {
            long long t = ei64[i];
            if (t < 0 || t >= N_NODES) ok = 0;
        }
        if (!ok) atomicOr(&bad, 1);
        __syncthreads();
        if (threadIdx.x == 0) g_flag = bad;
    }
}

// ===================== kernel 2: degcount || prepx || prepw (block ranges) ==
#define NB_CONV ((N_EDGES / 4 + 255) / 256)            // 1563 (4 edges/thread)
#define NB_PX   ((N_NODES * 26 + 255) / 256)           // 10157 (1 half2/thread)
#define NB_PW   ((256*64 + 256*256 + 128*256 + 255) / 256)  // 480

__global__ void k_mid(const void* __restrict__ ei,
                      const float* __restrict__ x,
                      const float* __restrict__ W1, const float* __restrict__ W2,
                      const float* __restrict__ W3) {
    int b = blockIdx.x;
    if (b < NB_CONV) {
        int e4 = b * 256 + threadIdx.x;
        if (e4 * 4 >= N_EDGES) return;
        int c[4];
        load4(ei, N_EDGES, e4, c);
        #pragma unroll
        for (int q = 0; q < 4; q++) atomicAdd(&g_deg[c[q]], 1);
    } else if (b < NB_CONV + NB_PX) {
        // ---- x -> fp16 padded [N][52], one half2 per thread ----
        int i = (b - NB_CONV) * 256 + threadIdx.x;
        if (i >= N_NODES * 26) return;
        int node = i / 26, c = i - node * 26;
        __half2 v;
        if (c < 25) {
            float2 f = *(const float2*)(x + (size_t)node * IN_F + c * 2);
            v = __floats2half2_rn(f.x, f.y);
        } else {
            v = __floats2half2_rn(0.f, 0.f);
        }
        *((__half2*)g_xh + i) = v;
    } else {
        // ---- weight prep fp16 transposed/padded ----
        int i = (b - NB_CONV - NB_PX) * 256 + threadIdx.x;
        if (i < 256 * 64) {
            int n = i >> 6, k = i & 63;
            g_W1[i] = __float2half((k < IN_F) ? W1[(size_t)k * 256 + n] : 0.f);
        } else if (i < 256 * 64 + 256 * 256) {
            int j = i - 256 * 64;
            int n = j >> 8, k = j & 255;
            g_W2[j] = __float2half(W2[(size_t)k * 256 + n]);
        } else if (i < 256 * 64 + 256 * 256 + 128 * 256) {
            int j = i - 256 * 64 - 256 * 256;
            int n = j >> 8, k = j & 255;
            g_W3[j] = __float2half((n < OUT_F) ? W3[(size_t)k * OUT_F + n] : 0.f);
        }
    }
}

// ===================== CSR range allocation (no scan): warp-agg atomic ======
// Writes g_cur[v] = beg so scatter's atomicAdd returns the slot directly.
__global__ void k_alloc() {
    int v = blockIdx.x * blockDim.x + threadIdx.x;
    int lane = threadIdx.x & 31;
    int d = (v < N_NODES) ? g_deg[v] : 1;
    if (v < N_NODES) g_dinv[v] = rsqrtf((float)d);
    int cnt = (v < N_NODES) ? (d - 1) : 0;
    int pre = cnt;
    #pragma unroll
    for (int o = 1; o < 32; o <<= 1) {
        int t = __shfl_up_sync(0xFFFFFFFFu, pre, o);
        if (lane >= o) pre += t;
    }
    int total = __shfl_sync(0xFFFFFFFFu, pre, 31);
    int base = 0;
    if (lane == 31 && total > 0) base = atomicAdd(&g_total, total);
    base = __shfl_sync(0xFFFFFFFFu, base, 31);
    if (v < N_NODES) {
        int beg = base + pre - cnt;
        g_beg[v] = beg;
        g_cur[v] = beg;
    }
}

// ===================== scatter: 4 edges/thread, direct atomic slot ==========
__global__ void k_scatter(const void* __restrict__ ei) {
    int e4 = blockIdx.x * blockDim.x + threadIdx.x;
    if (e4 * 4 >= N_EDGES) return;
    int r[4], c[4];
    load4(ei, 0, e4, r);
    load4(ei, N_EDGES, e4, c);
    int p[4];
    #pragma unroll
    for (int q = 0; q < 4; q++) p[q] = atomicAdd(&g_cur[c[q]], 1);
    #pragma unroll
    for (int q = 0; q < 4; q++) g_csr[p[q]] = r[q];
}

// ===================== aggregation (fp16 gather + fp16 out) =================
// layer-1 agg: xh fp16 [N][52] (half2 lanes), out fp16 [N][64]
__global__ void k_agg1() {
    const __half2* X2 = (const __half2*)g_xh;   // row stride 26
    int gw = (blockIdx.x * blockDim.x + threadIdx.x) >> 5;
    int lane = threadIdx.x & 31;
    if (gw >= N_NODES) return;
    int node = gw;
    bool act = lane < 25;
    int c2 = act ? lane : 0;
    float dv = g_dinv[node];
    float2 xv = __half22float2(X2[(size_t)node * 26 + c2]);
    float ax = dv * xv.x, ay = dv * xv.y;
    int beg = g_beg[node], end = beg + g_deg[node] - 1;
    int j = beg;
    for (; j + 4 <= end; j += 4) {
        int u0 = g_csr[j], u1 = g_csr[j + 1], u2 = g_csr[j + 2], u3 = g_csr[j + 3];
        float d0 = g_dinv[u0], d1 = g_dinv[u1], d2 = g_dinv[u2], d3 = g_dinv[u3];
        float2 a0 = __half22float2(X2[(size_t)u0 * 26 + c2]);
        float2 a1 = __half22float2(X2[(size_t)u1 * 26 + c2]);
        float2 a2 = __half22float2(X2[(size_t)u2 * 26 + c2]);
        float2 a3 = __half22float2(X2[(size_t)u3 * 26 + c2]);
        ax += d0 * a0.x; ay += d0 * a0.y;
        ax += d1 * a1.x; ay += d1 * a1.y;
        ax += d2 * a2.x; ay += d2 * a2.y;
        ax += d3 * a3.x; ay += d3 * a3.y;
    }
    for (; j < end; j++) {
        int u = g_csr[j];
        float d = g_dinv[u];
        float2 a = __half22float2(X2[(size_t)u * 26 + c2]);
        ax += d * a.x; ay += d * a.y;
    }
    float v0 = act ? dv * ax : 0.f;
    float v1 = act ? dv * ay : 0.f;
    *(__half2*)(g_A1 + (size_t)node * 64 + lane * 2) = __floats2half2_rn(v0, v1);
}

// layer-2 agg: single pass, uint4 lanes (8 halves), 32 lanes cover 256 cols.
__global__ void k_agg2() {
    const uint4* X = (const uint4*)g_h1h;       // row stride 32 uint4
    int gw = (blockIdx.x * blockDim.x + threadIdx.x) >> 5;
    int lane = threadIdx.x & 31;
    if (gw >= N_NODES) return;
    int node = gw;
    float dv = g_dinv[node];
    float a[8];
    {
        uint4 raw = X[(size_t)node * 32 + lane];
        float2 f0 = __half22float2(*(__half2*)&raw.x);
        float2 f1 = __half22float2(*(__half2*)&raw.y);
        float2 f2 = __half22float2(*(__half2*)&raw.z);
        float2 f3 = __half22float2(*(__half2*)&raw.w);
        a[0] = dv * f0.x; a[1] = dv * f0.y; a[2] = dv * f1.x; a[3] = dv * f1.y;
        a[4] = dv * f2.x; a[5] = dv * f2.y; a[6] = dv * f3.x; a[7] = dv * f3.y;
    }
    int beg = g_beg[node], end = beg + g_deg[node] - 1;
    int j = beg;
    for (; j + 4 <= end; j += 4) {
        int u0 = g_csr[j], u1 = g_csr[j + 1], u2 = g_csr[j + 2], u3 = g_csr[j + 3];
        float d0 = g_dinv[u0], d1 = g_dinv[u1], d2 = g_dinv[u2], d3 = g_dinv[u3];
        uint4 r0 = X[(size_t)u0 * 32 + lane];
        uint4 r1 = X[(size_t)u1 * 32 + lane];
        uint4 r2 = X[(size_t)u2 * 32 + lane];
        uint4 r3 = X[(size_t)u3 * 32 + lane];
        {
            float2 f0 = __half22float2(*(__half2*)&r0.x), f1 = __half22float2(*(__half2*)&r0.y);
            float2 f2 = __half22float2(*(__half2*)&r0.z), f3 = __half22float2(*(__half2*)&r0.w);
            a[0] += d0 * f0.x; a[1] += d0 * f0.y; a[2] += d0 * f1.x; a[3] += d0 * f1.y;
            a[4] += d0 * f2.x; a[5] += d0 * f2.y; a[6] += d0 * f3.x; a[7] += d0 * f3.y;
        }
        {
            float2 f0 = __half22float2(*(__half2*)&r1.x), f1 = __half22float2(*(__half2*)&r1.y);
            float2 f2 = __half22float2(*(__half2*)&r1.z), f3 = __half22float2(*(__half2*)&r1.w);
            a[0] += d1 * f0.x; a[1] += d1 * f0.y; a[2] += d1 * f1.x; a[3] += d1 * f1.y;
            a[4] += d1 * f2.x; a[5] += d1 * f2.y; a[6] += d1 * f3.x; a[7] += d1 * f3.y;
        }
        {
            float2 f0 = __half22float2(*(__half2*)&r2.x), f1 = __half22float2(*(__half2*)&r2.y);
            float2 f2 = __half22float2(*(__half2*)&r2.z), f3 = __half22float2(*(__half2*)&r2.w);
            a[0] += d2 * f0.x; a[1] += d2 * f0.y; a[2] += d2 * f1.x; a[3] += d2 * f1.y;
            a[4] += d2 * f2.x; a[5] += d2 * f2.y; a[6] += d2 * f3.x; a[7] += d2 * f3.y;
        }
        {
            float2 f0 = __half22float2(*(__half2*)&r3.x), f1 = __half22float2(*(__half2*)&r3.y);
            float2 f2 = __half22float2(*(__half2*)&r3.z), f3 = __half22float2(*(__half2*)&r3.w);
            a[0] += d3 * f0.x; a[1] += d3 * f0.y; a[2] += d3 * f1.x; a[3] += d3 * f1.y;
            a[4] += d3 * f2.x; a[5] += d3 * f2.y; a[6] += d3 * f3.x; a[7] += d3 * f3.y;
        }
    }
    for (; j < end; j++) {
        int u = g_csr[j];
        float d = g_dinv[u];
        uint4 r = X[(size_t)u * 32 + lane];
        float2 f0 = __half22float2(*(__half2*)&r.x), f1 = __half22float2(*(__half2*)&r.y);
        float2 f2 = __half22float2(*(__half2*)&r.z), f3 = __half22float2(*(__half2*)&r.w);
        a[0] += d * f0.x; a[1] += d * f0.y; a[2] += d * f1.x; a[3] += d * f1.y;
        a[4] += d * f2.x; a[5] += d * f2.y; a[6] += d * f3.x; a[7] += d * f3.y;
    }
    uint4 outv;
    *(__half2*)&outv.x = __floats2half2_rn(a[0] * dv, a[1] * dv);
    *(__half2*)&outv.y = __floats2half2_rn(a[2] * dv, a[3] * dv);
    *(__half2*)&outv.z = __floats2half2_rn(a[4] * dv, a[5] * dv);
    *(__half2*)&outv.w = __floats2half2_rn(a[6] * dv, a[7] * dv);
    *(uint4*)(g_A2 + (size_t)node * 256 + lane * 8) = outv;
}

// final agg: t3 fp16 [N][128] (uint2 lanes), +bias, out [N][121] fp32
__global__ void k_agg_out(float* __restrict__ OUT, const float* __restrict__ bias) {
    const uint2* X4 = (const uint2*)g_t3h;      // row stride 32 uint2
    int gw = (blockIdx.x * blockDim.x + threadIdx.x) >> 5;
    int lane = threadIdx.x & 31;
    if (gw >= N_NODES) return;
    int node = gw;
    float dv = g_dinv[node];
    uint2 raw = X4[(size_t)node * 32 + lane];
    float2 f01 = __half22float2(*(__half2*)&raw.x);
    float2 f23 = __half22float2(*(__half2*)&raw.y);
    float a0 = dv * f01.x, a1 = dv * f01.y, a2 = dv * f23.x, a3 = dv * f23.y;
    int beg = g_beg[node], end = beg + g_deg[node] - 1;
    int j = beg;
    for (; j + 4 <= end; j += 4) {
        int u0 = g_csr[j], u1 = g_csr[j + 1], u2 = g_csr[j + 2], u3 = g_csr[j + 3];
        float d0 = g_dinv[u0], d1 = g_dinv[u1], d2 = g_dinv[u2], d3 = g_dinv[u3];
        uint2 r0 = X4[(size_t)u0 * 32 + lane];
        uint2 r1 = X4[(size_t)u1 * 32 + lane];
        uint2 r2 = X4[(size_t)u2 * 32 + lane];
        uint2 r3 = X4[(size_t)u3 * 32 + lane];
        float2 p0a = __half22float2(*(__half2*)&r0.x), p0b = __half22float2(*(__half2*)&r0.y);
        float2 p1a = __half22float2(*(__half2*)&r1.x), p1b = __half22float2(*(__half2*)&r1.y);
        float2 p2a = __half22float2(*(__half2*)&r2.x), p2b = __half22float2(*(__half2*)&r2.y);
        float2 p3a = __half22float2(*(__half2*)&r3.x), p3b = __half22float2(*(__half2*)&r3.y);
        a0 += d0 * p0a.x; a1 += d0 * p0a.y; a2 += d0 * p0b.x; a3 += d0 * p0b.y;
        a0 += d1 * p1a.x; a1 += d1 * p1a.y; a2 += d1 * p1b.x; a3 += d1 * p1b.y;
        a0 += d2 * p2a.x; a1 += d2 * p2a.y; a2 += d2 * p2b.x; a3 += d2 * p2b.y;
        a0 += d3 * p3a.x; a1 += d3 * p3a.y; a2 += d3 * p3b.x; a3 += d3 * p3b.y;
    }
    for (; j < end; j++) {
        int u = g_csr[j];
        float d = g_dinv[u];
        uint2 r = X4[(size_t)u * 32 + lane];
        float2 pa = __half22float2(*(__half2*)&r.x), pb = __half22float2(*(__half2*)&r.y);
        a0 += d * pa.x; a1 += d * pa.y; a2 += d * pb.x; a3 += d * pb.y;
    }
    int c = lane * 4;
    float* dst = OUT + (size_t)node * OUT_F;
    if (c + 0 < OUT_F) dst[c + 0] = dv * a0 + bias[c + 0];
    if (c + 1 < OUT_F) dst[c + 1] = dv * a1 + bias[c + 1];
    if (c + 2 < OUT_F) dst[c + 2] = dv * a2 + bias[c + 2];
    if (c + 3 < OUT_F) dst[c + 3] = dv * a3 + bias[c + 3];
}

// ===================== warp-MMA GEMM (fp16, BK=64, 2-stage cp.async) ========
template<int KT, int NNTOT, bool BIAS, bool RELU>
__global__ void __launch_bounds__(256, 2)
k_mma(const __half* __restrict__ A, const __half* __restrict__ B,
      const float* __restrict__ bias, __half* __restrict__ C) {
    constexpr int ASTR = KT * 64;
    constexpr int PAD = 72;                  // 64 + 8 halves (conflict-free)
    constexpr int ST = 128 * PAD;            // elements per array per stage
    extern __shared__ __half dsm[];

    const int tid = threadIdx.x;
    const int wid = tid >> 5, lane = tid & 31;
    const int wm = wid & 3, wn = wid >> 2;
    const int m0 = blockIdx.x * 128;
    const int n0 = blockIdx.y * 128;

    float acc[2][8][4];
    #pragma unroll
    for (int mt = 0; mt < 2; mt++)
        #pragma unroll
        for (int nt = 0; nt < 8; nt++)
            #pragma unroll
            for (int q = 0; q < 4; q++) acc[mt][nt][q] = 0.f;

    auto stage = [&](int s, int c) {
        __half* base = dsm + s * 2 * ST;
        #pragma unroll
        for (int it = 0; it < 4; it++) {
            int idx = it * 256 + tid;        // 0..1023: row=idx>>3, chk=idx&7
            int row = idx >> 3, chk = idx & 7;
            int m = m0 + row; if (m >= N_NODES) m = N_NODES - 1;
            size_t goA = (size_t)m * ASTR + c * 64 + chk * 8;
            size_t goB = (size_t)(n0 + row) * ASTR + c * 64 + chk * 8;
            int so = row * PAD + chk * 8;
            CP_ASYNC16(smem_u32(base + so), A + goA);
            CP_ASYNC16(smem_u32(base + ST + so), B + goB);
        }
        CP_COMMIT();
    };

    stage(0, 0);
    for (int c = 0; c < KT; c++) {
        if (c + 1 < KT) {
            stage((c + 1) & 1, c + 1);
            asm volatile("cp.async.wait_group 1;" ::: "memory");
        } else {
            asm volatile("cp.async.wait_group 0;" ::: "memory");
        }
        __syncthreads();

        const __half* sA = dsm + (c & 1) * 2 * ST;
        const __half* sB = sA + ST;

        #pragma unroll
        for (int ks = 0; ks < 4; ks++) {
            const int kc = ks * 16;
            uint32_t a_f[2][4];
            #pragma unroll
            for (int mt = 0; mt < 2; mt++) {
                int r = wm * 32 + mt * 16 + (lane & 15);
                int cA = kc + ((lane >> 4) << 3);
                LDM_X4(a_f[mt], smem_u32(sA + r * PAD + cA));
            }
            #pragma unroll
            for (int ntp = 0; ntp < 4; ntp++) {
                int br = wn * 64 + ntp * 16 + (lane & 7) + ((lane & 16) ? 8 : 0);
                int cB = kc + ((lane & 8) ? 8 : 0);
                uint32_t b_f[4];
                LDM_X4(b_f, smem_u32(sB + br * PAD + cB));
                #pragma unroll
                for (int half = 0; half < 2; half++) {
                    int nt = ntp * 2 + half;
                    #pragma unroll
                    for (int mt = 0; mt < 2; mt++)
                        mma16816h(acc[mt][nt], a_f[mt], b_f + 2 * half);
                }
            }
        }
        __syncthreads();
    }

    #pragma unroll
    for (int mt = 0; mt < 2; mt++) {
        int mrow = m0 + wm * 32 + mt * 16 + (lane >> 2);
        #pragma unroll
        for (int nt = 0; nt < 8; nt++) {
            int n = n0 + wn * 64 + nt * 8 + (lane & 3) * 2;
            float v0 = acc[mt][nt][0], v1 = acc[mt][nt][1];
            float v2 = acc[mt][nt][2], v3 = acc[mt][nt][3];
            if (BIAS) {
                float bb0 = bias[n], bb1 = bias[n + 1];
                v0 += bb0; v1 += bb1; v2 += bb0; v3 += bb1;
            }
            if (RELU) {
                v0 = fmaxf(v0, 0.f); v1 = fmaxf(v1, 0.f);
                v2 = fmaxf(v2, 0.f); v3 = fmaxf(v3, 0.f);
            }
            if (mrow < N_NODES)
                *(__half2*)(C + (size_t)mrow * NNTOT + n) = __floats2half2_rn(v0, v1);
            if (mrow + 8 < N_NODES)
                *(__half2*)(C + (size_t)(mrow + 8) * NNTOT + n) = __floats2half2_rn(v2, v3);
        }
    }
}

// ===================== launch ===============================================
static inline void* sym(const void* s) {
    void* p = nullptr;
    cudaGetSymbolAddress(&p, s);
    return p;
}

extern "C" void kernel_launch(void* const* d_in, const int* in_sizes, int n_in,
                              void* d_out, int out_size) {
    const float* x   = (const float*)d_in[0];
    const void*  ei  = d_in[1];
    const float* W1  = (const float*)d_in[2];
    const float* b1  = (const float*)d_in[3];
    const float* W2  = (const float*)d_in[4];
    const float* b2  = (const float*)d_in[5];
    const float* W3  = (const float*)d_in[6];
    const float* b3  = (const float*)d_in[7];
    float*       out = (float*)d_out;

    __half* pW1 = (__half*)sym(g_W1);
    __half* pW2 = (__half*)sym(g_W2);
    __half* pW3 = (__half*)sym(g_W3);
    __half* A1  = (__half*)sym(g_A1);
    __half* A2  = (__half*)sym(g_A2);
    __half* A3  = (__half*)sym(g_A3);
    __half* h1h = (__half*)sym(g_h1h);
    __half* t3h = (__half*)sym(g_t3h);

    const int NB_N = (N_NODES + 255) / 256;

    const int SMEM_MMA = 2 * 2 * 128 * 72 * (int)sizeof(__half);  // 73728
    cudaFuncSetAttribute(k_mma<1, 256, true,  true >, cudaFuncAttributeMaxDynamicSharedMemorySize, SMEM_MMA);
    cudaFuncSetAttribute(k_mma<4, 256, true,  true >, cudaFuncAttributeMaxDynamicSharedMemorySize, SMEM_MMA);
    cudaFuncSetAttribute(k_mma<4, 128, false, false>, cudaFuncAttributeMaxDynamicSharedMemorySize, SMEM_MMA);

    // preprocessing: detect+init -> (degcount||prepx||prepw) -> alloc -> scatter
    k_front  <<<NB_N, 256>>>((const long long*)ei);
    k_mid    <<<NB_CONV + NB_PX + NB_PW, 256>>>(ei, x, W1, W2, W3);
    k_alloc  <<<NB_N, 256>>>();
    k_scatter<<<(N_EDGES / 4 + 255) / 256, 256>>>(ei);

    // Layer 1: agg(xh) -> A1; GEMM K=64 -> h1 fp16 (+b1, relu)
    k_agg1<<<(N_NODES * 32 + 255) / 256, 256>>>();
    {
        dim3 grid(M_TILES, 2);
        k_mma<1, 256, true, true><<<grid, 256, SMEM_MMA>>>(A1, pW1, b1, h1h);
    }

    // Layer 2: agg(h1) single-pass -> A2; GEMM K=256 -> A3 fp16 (+b2, relu)
    k_agg2<<<(N_NODES * 32 + 255) / 256, 256>>>();
    {
        dim3 grid(M_TILES, 2);
        k_mma<4, 256, true, true><<<grid, 256, SMEM_MMA>>>(A2, pW2, b2, A3);
    }

    // Layer 3: GEMM K=256 -> t3 fp16; agg(t3)+b3 -> out fp32
    {
        dim3 grid(M_TILES, 1);
        k_mma<4, 128, false, false><<<grid, 256, SMEM_MMA>>>(A3, pW3, nullptr, t3h);
    }
    k_agg_out<<<(N_NODES * 32 + 255) / 256, 256>>>(out, b3);
}

// round 16
// speedup vs baseline: 1.0252x; 1.0063x over previous
#include <cuda_runtime.h>
#include <cuda_fp16.h>
#include <stdint.h>

#define N_NODES 100000
#define N_EDGES 1600000
#define IN_F 50
#define HID 256
#define OUT_F 121
#define M_TILES ((N_NODES + 127) / 128)   // 782

// ===================== scratch (static __device__) ==========================
__device__ int   g_flag;
__device__ int   g_total;
__device__ int   g_deg[N_NODES];
__device__ int   g_beg[N_NODES];
__device__ float g_dinv[N_NODES];
__device__ int   g_cur[N_NODES];
__device__ int   g_csr[N_EDGES];

__device__ __half g_W1[256 * 64];     // W1^T padded K->64  [n][k]
__device__ __half g_W2[256 * 256];    // W2^T
__device__ __half g_W3[128 * 256];    // W3^T padded N->128

__device__ __half g_A1[(size_t)N_NODES * 64];    // agg1 out (GEMM1 A)
__device__ __half g_A2[(size_t)N_NODES * 256];   // agg2 out (GEMM2 A)
__device__ __half g_A3[(size_t)N_NODES * 256];   // relu(GEMM2 out) (GEMM3 A)
__device__ __half g_xh [(size_t)N_NODES * 52];   // x fp16, padded 50->52
__device__ __half g_h1h[(size_t)N_NODES * 256];  // h1 fp16 (51.2MB: L2-resident)
__device__ __half g_t3h[(size_t)N_NODES * 128];  // t3 fp16 (25.6MB: L2-resident)

// ===================== small PTX helpers (baseline features only) ===========
__device__ __forceinline__ uint32_t smem_u32(const void* p) {
    uint32_t a;
    asm("{ .reg .u64 t; cvta.to.shared.u64 t, %1; cvt.u32.u64 %0, t; }" : "=r"(a) : "l"(p));
    return a;
}

#define CP_ASYNC16(dst_u32, src_ptr) \
    asm volatile("cp.async.cg.shared.global [%0], [%1], 16;" :: "r"(dst_u32), "l"(src_ptr))
#define CP_COMMIT() asm volatile("cp.async.commit_group;" ::: "memory")

#define LDM_X4(R, ADDR) \
    asm volatile("ldmatrix.sync.aligned.m8n8.x4.shared.b16 {%0,%1,%2,%3}, [%4];" \
        : "=r"((R)[0]), "=r"((R)[1]), "=r"((R)[2]), "=r"((R)[3]) : "r"(ADDR))

__device__ __forceinline__ void mma16816h(float* d, const uint32_t* a, const uint32_t* b) {
    asm volatile(
        "mma.sync.aligned.m16n8k16.row.col.f32.f16.f16.f32 "
        "{%0,%1,%2,%3}, {%4,%5,%6,%7}, {%8,%9}, {%0,%1,%2,%3};"
        : "+f"(d[0]), "+f"(d[1]), "+f"(d[2]), "+f"(d[3])
        : "r"(a[0]), "r"(a[1]), "r"(a[2]), "r"(a[3]), "r"(b[0]), "r"(b[1]));
}

// ===================== helpers: load 4 edge indices =========================
__device__ __forceinline__ void load4(const void* ei, size_t elem_off, int e4,
                                      int* v) {
    if (g_flag) {
        int4 a = ((const int4*)((const int*)ei + elem_off))[e4];
        v[0] = a.x; v[1] = a.y; v[2] = a.z; v[3] = a.w;
    } else {
        const longlong2* p = (const longlong2*)((const long long*)ei + elem_off);
        longlong2 a = p[e4 * 2], b = p[e4 * 2 + 1];
        v[0] = (int)a.x; v[1] = (int)a.y; v[2] = (int)b.x; v[3] = (int)b.y;
    }
}

// ===================== kernel 1: detect (block 0) + init (all blocks) =======
__global__ void k_front(const long long* __restrict__ ei64) {
    int v = blockIdx.x * blockDim.x + threadIdx.x;
    if (v < N_NODES) g_deg[v] = 1;
    if (blockIdx.x == 0) {
        __shared__ int bad;
        if (threadIdx.x == 0) { bad = 0; g_total = 0; }
        __syncthreads();
        int ok = 1;
        for (int i = threadIdx.x; i < 4096; i += 256) {
            long long t = ei64[i];
            if (t < 0 || t >= N_NODES) ok = 0;
        }
        if (!ok) atomicOr(&bad, 1);
        __syncthreads();
        if (threadIdx.x == 0) g_flag = bad;
    }
}

// ===================== kernel 2: degcount || prepx || prepw (block ranges) ==
#define NB_CONV ((N_EDGES / 4 + 255) / 256)            // 1563 (4 edges/thread)
#define NB_PX   ((N_NODES * 13 + 255) / 256)           // 5079 (2 half2/thread)
#define NB_PW   ((256*64 + 256*256 + 128*256 + 255) / 256)  // 480

__global__ void k_mid(const void* __restrict__ ei,
                      const float* __restrict__ x,
                      const float* __restrict__ W1, const float* __restrict__ W2,
                      const float* __restrict__ W3) {
    int b = blockIdx.x;
    if (b < NB_CONV) {
        int e4 = b * 256 + threadIdx.x;
        if (e4 * 4 >= N_EDGES) return;
        int c[4];
        load4(ei, N_EDGES, e4, c);
        #pragma unroll
        for (int q = 0; q < 4; q++) atomicAdd(&g_deg[c[q]], 1);
    } else if (b < NB_CONV + NB_PX) {
        // ---- x -> fp16 padded [N][52], two half2 per thread ----
        int t = (b - NB_CONV) * 256 + threadIdx.x;   // pair index over N*13
        if (t >= N_NODES * 13) return;
        int node = t / 13, cp = t - node * 13;       // cp: 0..12, covers cols 4cp..4cp+3
        __half2 v0, v1;
        int c0 = cp * 4;
        if (c0 + 1 < IN_F) {
            float2 f = *(const float2*)(x + (size_t)node * IN_F + c0);
            v0 = __floats2half2_rn(f.x, f.y);
        } else v0 = __floats2half2_rn(0.f, 0.f);
        if (c0 + 3 < IN_F) {
            float2 f = *(const float2*)(x + (size_t)node * IN_F + c0 + 2);
            v1 = __floats2half2_rn(f.x, f.y);
        } else if (c0 + 2 < IN_F) {
            v1 = __floats2half2_rn(x[(size_t)node * IN_F + c0 + 2], 0.f);
        } else v1 = __floats2half2_rn(0.f, 0.f);
        __half2* dst = (__half2*)(g_xh + (size_t)node * 52 + c0);
        dst[0] = v0;
        dst[1] = v1;
    } else {
        // ---- weight prep fp16 transposed/padded ----
        int i = (b - NB_CONV - NB_PX) * 256 + threadIdx.x;
        if (i < 256 * 64) {
            int n = i >> 6, k = i & 63;
            g_W1[i] = __float2half((k < IN_F) ? W1[(size_t)k * 256 + n] : 0.f);
        } else if (i < 256 * 64 + 256 * 256) {
            int j = i - 256 * 64;
            int n = j >> 8, k = j & 255;
            g_W2[j] = __float2half(W2[(size_t)k * 256 + n]);
        } else if (i < 256 * 64 + 256 * 256 + 128 * 256) {
            int j = i - 256 * 64 - 256 * 256;
            int n = j >> 8, k = j & 255;
            g_W3[j] = __float2half((n < OUT_F) ? W3[(size_t)k * OUT_F + n] : 0.f);
        }
    }
}

// ===================== CSR range allocation (no scan): warp-agg atomic ======
__global__ void k_alloc() {
    int v = blockIdx.x * blockDim.x + threadIdx.x;
    int lane = threadIdx.x & 31;
    int d = (v < N_NODES) ? g_deg[v] : 1;
    if (v < N_NODES) g_dinv[v] = rsqrtf((float)d);
    int cnt = (v < N_NODES) ? (d - 1) : 0;
    int pre = cnt;
    #pragma unroll
    for (int o = 1; o < 32; o <<= 1) {
        int t = __shfl_up_sync(0xFFFFFFFFu, pre, o);
        if (lane >= o) pre += t;
    }
    int total = __shfl_sync(0xFFFFFFFFu, pre, 31);
    int base = 0;
    if (lane == 31 && total > 0) base = atomicAdd(&g_total, total);
    base = __shfl_sync(0xFFFFFFFFu, base, 31);
    if (v < N_NODES) {
        int beg = base + pre - cnt;
        g_beg[v] = beg;
        g_cur[v] = beg;
    }
}

// ===================== scatter: 4 edges/thread, direct atomic slot ==========
__global__ void k_scatter(const void* __restrict__ ei) {
    int e4 = blockIdx.x * blockDim.x + threadIdx.x;
    if (e4 * 4 >= N_EDGES) return;
    int r[4], c[4];
    load4(ei, 0, e4, r);
    load4(ei, N_EDGES, e4, c);
    int p[4];
    #pragma unroll
    for (int q = 0; q < 4; q++) p[q] = atomicAdd(&g_cur[c[q]], 1);
    #pragma unroll
    for (int q = 0; q < 4; q++) g_csr[p[q]] = r[q];
}

// ===================== aggregation (fp16 gather + fp16 out) =================
// layer-1 agg: xh fp16 [N][52] (half2 lanes), out fp16 [N][64]
__global__ void k_agg1() {
    const __half2* X2 = (const __half2*)g_xh;   // row stride 26
    int gw = (blockIdx.x * blockDim.x + threadIdx.x) >> 5;
    int lane = threadIdx.x & 31;
    if (gw >= N_NODES) return;
    int node = gw;
    bool act = lane < 25;
    int c2 = act ? lane : 0;
    float dv = g_dinv[node];
    float2 xv = __half22float2(X2[(size_t)node * 26 + c2]);
    float ax = dv * xv.x, ay = dv * xv.y;
    int beg = g_beg[node], end = beg + g_deg[node] - 1;
    int j = beg;
    for (; j + 4 <= end; j += 4) {
        int u0 = g_csr[j], u1 = g_csr[j + 1], u2 = g_csr[j + 2], u3 = g_csr[j + 3];
        float d0 = g_dinv[u0], d1 = g_dinv[u1], d2 = g_dinv[u2], d3 = g_dinv[u3];
        float2 a0 = __half22float2(X2[(size_t)u0 * 26 + c2]);
        float2 a1 = __half22float2(X2[(size_t)u1 * 26 + c2]);
        float2 a2 = __half22float2(X2[(size_t)u2 * 26 + c2]);
        float2 a3 = __half22float2(X2[(size_t)u3 * 26 + c2]);
        ax += d0 * a0.x; ay += d0 * a0.y;
        ax += d1 * a1.x; ay += d1 * a1.y;
        ax += d2 * a2.x; ay += d2 * a2.y;
        ax += d3 * a3.x; ay += d3 * a3.y;
    }
    for (; j < end; j++) {
        int u = g_csr[j];
        float d = g_dinv[u];
        float2 a = __half22float2(X2[(size_t)u * 26 + c2]);
        ax += d * a.x; ay += d * a.y;
    }
    float v0 = act ? dv * ax : 0.f;
    float v1 = act ? dv * ay : 0.f;
    *(__half2*)(g_A1 + (size_t)node * 64 + lane * 2) = __floats2half2_rn(v0, v1);
}

// layer-2 agg: single pass, uint4 lanes (8 halves), 32 lanes cover 256 cols.
__global__ void k_agg2() {
    const uint4* X = (const uint4*)g_h1h;       // row stride 32 uint4
    int gw = (blockIdx.x * blockDim.x + threadIdx.x) >> 5;
    int lane = threadIdx.x & 31;
    if (gw >= N_NODES) return;
    int node = gw;
    float dv = g_dinv[node];
    float a[8];
    {
        uint4 raw = X[(size_t)node * 32 + lane];
        float2 f0 = __half22float2(*(__half2*)&raw.x);
        float2 f1 = __half22float2(*(__half2*)&raw.y);
        float2 f2 = __half22float2(*(__half2*)&raw.z);
        float2 f3 = __half22float2(*(__half2*)&raw.w);
        a[0] = dv * f0.x; a[1] = dv * f0.y; a[2] = dv * f1.x; a[3] = dv * f1.y;
        a[4] = dv * f2.x; a[5] = dv * f2.y; a[6] = dv * f3.x; a[7] = dv * f3.y;
    }
    int beg = g_beg[node], end = beg + g_deg[node] - 1;
    int j = beg;
    for (; j + 4 <= end; j += 4) {
        int u0 = g_csr[j], u1 = g_csr[j + 1], u2 = g_csr[j + 2], u3 = g_csr[j + 3];
        float d0 = g_dinv[u0], d1 = g_dinv[u1], d2 = g_dinv[u2], d3 = g_dinv[u3];
        uint4 r0 = X[(size_t)u0 * 32 + lane];
        uint4 r1 = X[(size_t)u1 * 32 + lane];
        uint4 r2 = X[(size_t)u2 * 32 + lane];
        uint4 r3 = X[(size_t)u3 * 32 + lane];
        {
            float2 f0 = __half22float2(*(__half2*)&r0.x), f1 = __half22float2(*(__half2*)&r0.y);
            float2 f2 = __half22float2(*(__half2*)&r0.z), f3 = __half22float2(*(__half2*)&r0.w);
            a[0] += d0 * f0.x; a[1] += d0 * f0.y; a[2] += d0 * f1.x; a[3] += d0 * f1.y;
            a[4] += d0 * f2.x; a[5] += d0 * f2.y; a[6] += d0 * f3.x; a[7] += d0 * f3.y;
        }
        {
            float2 f0 = __half22float2(*(__half2*)&r1.x), f1 = __half22float2(*(__half2*)&r1.y);
            float2 f2 = __half22float2(*(__half2*)&r1.z), f3 = __half22float2(*(__half2*)&r1.w);
            a[0] += d1 * f0.x; a[1] += d1 * f0.y; a[2] += d1 * f1.x; a[3] += d1 * f1.y;
            a[4] += d1 * f2.x; a[5] += d1 * f2.y; a[6] += d1 * f3.x; a[7] += d1 * f3.y;
        }
        {
            float2 f0 = __half22float2(*(__half2*)&r2.x), f1 = __half22float2(*(__half2*)&r2.y);
            float2 f2 = __half22float2(*(__half2*)&r2.z), f3 = __half22float2(*(__half2*)&r2.w);
            a[0] += d2 * f0.x; a[1] += d2 * f0.y; a[2] += d2 * f1.x; a[3] += d2 * f1.y;
            a[4] += d2 * f2.x; a[5] += d2 * f2.y; a[6] += d2 * f3.x; a[7] += d2 * f3.y;
        }
        {
            float2 f0 = __half22float2(*(__half2*)&r3.x), f1 = __half22float2(*(__half2*)&r3.y);
            float2 f2 = __half22float2(*(__half2*)&r3.z), f3 = __half22float2(*(__half2*)&r3.w);
            a[0] += d3 * f0.x; a[1] += d3 * f0.y; a[2] += d3 * f1.x; a[3] += d3 * f1.y;
            a[4] += d3 * f2.x; a[5] += d3 * f2.y; a[6] += d3 * f3.x; a[7] += d3 * f3.y;
        }
    }
    for (; j < end; j++) {
        int u = g_csr[j];
        float d = g_dinv[u];
        uint4 r = X[(size_t)u * 32 + lane];
        float2 f0 = __half22float2(*(__half2*)&r.x), f1 = __half22float2(*(__half2*)&r.y);
        float2 f2 = __half22float2(*(__half2*)&r.z), f3 = __half22float2(*(__half2*)&r.w);
        a[0] += d * f0.x; a[1] += d * f0.y; a[2] += d * f1.x; a[3] += d * f1.y;
        a[4] += d * f2.x; a[5] += d * f2.y; a[6] += d * f3.x; a[7] += d * f3.y;
    }
    uint4 outv;
    *(__half2*)&outv.x = __floats2half2_rn(a[0] * dv, a[1] * dv);
    *(__half2*)&outv.y = __floats2half2_rn(a[2] * dv, a[3] * dv);
    *(__half2*)&outv.z = __floats2half2_rn(a[4] * dv, a[5] * dv);
    *(__half2*)&outv.w = __floats2half2_rn(a[6] * dv, a[7] * dv);
    *(uint4*)(g_A2 + (size_t)node * 256 + lane * 8) = outv;
}

// final agg: t3 fp16 [N][128] (uint2 lanes), +bias, out [N][121] fp32
__global__ void k_agg_out(float* __restrict__ OUT, const float* __restrict__ bias) {
    const uint2* X4 = (const uint2*)g_t3h;      // row stride 32 uint2
    int gw = (blockIdx.x * blockDim.x + threadIdx.x) >> 5;
    int lane = threadIdx.x & 31;
    if (gw >= N_NODES) return;
    int node = gw;
    float dv = g_dinv[node];
    uint2 raw = X4[(size_t)node * 32 + lane];
    float2 f01 = __half22float2(*(__half2*)&raw.x);
    float2 f23 = __half22float2(*(__half2*)&raw.y);
    float a0 = dv * f01.x, a1 = dv * f01.y, a2 = dv * f23.x, a3 = dv * f23.y;
    int beg = g_beg[node], end = beg + g_deg[node] - 1;
    int j = beg;
    for (; j + 4 <= end; j += 4) {
        int u0 = g_csr[j], u1 = g_csr[j + 1], u2 = g_csr[j + 2], u3 = g_csr[j + 3];
        float d0 = g_dinv[u0], d1 = g_dinv[u1], d2 = g_dinv[u2], d3 = g_dinv[u3];
        uint2 r0 = X4[(size_t)u0 * 32 + lane];
        uint2 r1 = X4[(size_t)u1 * 32 + lane];
        uint2 r2 = X4[(size_t)u2 * 32 + lane];
        uint2 r3 = X4[(size_t)u3 * 32 + lane];
        float2 p0a = __half22float2(*(__half2*)&r0.x), p0b = __half22float2(*(__half2*)&r0.y);
        float2 p1a = __half22float2(*(__half2*)&r1.x), p1b = __half22float2(*(__half2*)&r1.y);
        float2 p2a = __half22float2(*(__half2*)&r2.x), p2b = __half22float2(*(__half2*)&r2.y);
        float2 p3a = __half22float2(*(__half2*)&r3.x), p3b = __half22float2(*(__half2*)&r3.y);
        a0 += d0 * p0a.x; a1 += d0 * p0a.y; a2 += d0 * p0b.x; a3 += d0 * p0b.y;
        a0 += d1 * p1a.x; a1 += d1 * p1a.y; a2 += d1 * p1b.x; a3 += d1 * p1b.y;
        a0 += d2 * p2a.x; a1 += d2 * p2a.y; a2 += d2 * p2b.x; a3 += d2 * p2b.y;
        a0 += d3 * p3a.x; a1 += d3 * p3a.y; a2 += d3 * p3b.x; a3 += d3 * p3b.y;
    }
    for (; j < end; j++) {
        int u = g_csr[j];
        float d = g_dinv[u];
        uint2 r = X4[(size_t)u * 32 + lane];
        float2 pa = __half22float2(*(__half2*)&r.x), pb = __half22float2(*(__half2*)&r.y);
        a0 += d * pa.x; a1 += d * pa.y; a2 += d * pb.x; a3 += d * pb.y;
    }
    int c = lane * 4;
    float* dst = OUT + (size_t)node * OUT_F;
    if (c + 0 < OUT_F) dst[c + 0] = dv * a0 + bias[c + 0];
    if (c + 1 < OUT_F) dst[c + 1] = dv * a1 + bias[c + 1];
    if (c + 2 < OUT_F) dst[c + 2] = dv * a2 + bias[c + 2];
    if (c + 3 < OUT_F) dst[c + 3] = dv * a3 + bias[c + 3];
}

// ===================== warp-MMA GEMM (fp16, BK=64, 2-stage cp.async) ========
// Grid is (NSPLIT, M_TILES): adjacent blocks share the same A slab -> the
// second N-block's A reads hit L2 (A-tile reuse).
template<int KT, int NNTOT, bool BIAS, bool RELU>
__global__ void __launch_bounds__(256, 2)
k_mma(const __half* __restrict__ A, const __half* __restrict__ B,
      const float* __restrict__ bias, __half* __restrict__ C) {
    constexpr int ASTR = KT * 64;
    constexpr int PAD = 72;                  // 64 + 8 halves (conflict-free)
    constexpr int ST = 128 * PAD;            // elements per array per stage
    extern __shared__ __half dsm[];

    const int tid = threadIdx.x;
    const int wid = tid >> 5, lane = tid & 31;
    const int wm = wid & 3, wn = wid >> 2;
    const int m0 = blockIdx.y * 128;         // swapped: y = M tile (slow)
    const int n0 = blockIdx.x * 128;         //          x = N tile (fast)

    float acc[2][8][4];
    #pragma unroll
    for (int mt = 0; mt < 2; mt++)
        #pragma unroll
        for (int nt = 0; nt < 8; nt++)
            #pragma unroll
            for (int q = 0; q < 4; q++) acc[mt][nt][q] = 0.f;

    auto stage = [&](int s, int c) {
        __half* base = dsm + s * 2 * ST;
        #pragma unroll
        for (int it = 0; it < 4; it++) {
            int idx = it * 256 + tid;        // 0..1023: row=idx>>3, chk=idx&7
            int row = idx >> 3, chk = idx & 7;
            int m = m0 + row; if (m >= N_NODES) m = N_NODES - 1;
            size_t goA = (size_t)m * ASTR + c * 64 + chk * 8;
            size_t goB = (size_t)(n0 + row) * ASTR + c * 64 + chk * 8;
            int so = row * PAD + chk * 8;
            CP_ASYNC16(smem_u32(base + so), A + goA);
            CP_ASYNC16(smem_u32(base + ST + so), B + goB);
        }
        CP_COMMIT();
    };

    stage(0, 0);
    for (int c = 0; c < KT; c++) {
        if (c + 1 < KT) {
            stage((c + 1) & 1, c + 1);
            asm volatile("cp.async.wait_group 1;" ::: "memory");
        } else {
            asm volatile("cp.async.wait_group 0;" ::: "memory");
        }
        __syncthreads();

        const __half* sA = dsm + (c & 1) * 2 * ST;
        const __half* sB = sA + ST;

        #pragma unroll
        for (int ks = 0; ks < 4; ks++) {
            const int kc = ks * 16;
            uint32_t a_f[2][4];
            #pragma unroll
            for (int mt = 0; mt < 2; mt++) {
                int r = wm * 32 + mt * 16 + (lane & 15);
                int cA = kc + ((lane >> 4) << 3);
                LDM_X4(a_f[mt], smem_u32(sA + r * PAD + cA));
            }
            #pragma unroll
            for (int ntp = 0; ntp < 4; ntp++) {
                int br = wn * 64 + ntp * 16 + (lane & 7) + ((lane & 16) ? 8 : 0);
                int cB = kc + ((lane & 8) ? 8 : 0);
                uint32_t b_f[4];
                LDM_X4(b_f, smem_u32(sB + br * PAD + cB));
                #pragma unroll
                for (int half = 0; half < 2; half++) {
                    int nt = ntp * 2 + half;
                    #pragma unroll
                    for (int mt = 0; mt < 2; mt++)
                        mma16816h(acc[mt][nt], a_f[mt], b_f + 2 * half);
                }
            }
        }
        __syncthreads();
    }

    #pragma unroll
    for (int mt = 0; mt < 2; mt++) {
        int mrow = m0 + wm * 32 + mt * 16 + (lane >> 2);
        #pragma unroll
        for (int nt = 0; nt < 8; nt++) {
            int n = n0 + wn * 64 + nt * 8 + (lane & 3) * 2;
            float v0 = acc[mt][nt][0], v1 = acc[mt][nt][1];
            float v2 = acc[mt][nt][2], v3 = acc[mt][nt][3];
            if (BIAS) {
                float bb0 = bias[n], bb1 = bias[n + 1];
                v0 += bb0; v1 += bb1; v2 += bb0; v3 += bb1;
            }
            if (RELU) {
                v0 = fmaxf(v0, 0.f); v1 = fmaxf(v1, 0.f);
                v2 = fmaxf(v2, 0.f); v3 = fmaxf(v3, 0.f);
            }
            if (mrow < N_NODES)
                *(__half2*)(C + (size_t)mrow * NNTOT + n) = __floats2half2_rn(v0, v1);
            if (mrow + 8 < N_NODES)
                *(__half2*)(C + (size_t)(mrow + 8) * NNTOT + n) = __floats2half2_rn(v2, v3);
        }
    }
}

// ===================== launch ===============================================
static inline void* sym(const void* s) {
    void* p = nullptr;
    cudaGetSymbolAddress(&p, s);
    return p;
}

extern "C" void kernel_launch(void* const* d_in, const int* in_sizes, int n_in,
                              void* d_out, int out_size) {
    const float* x   = (const float*)d_in[0];
    const void*  ei  = d_in[1];
    const float* W1  = (const float*)d_in[2];
    const float* b1  = (const float*)d_in[3];
    const float* W2  = (const float*)d_in[4];
    const float* b2  = (const float*)d_in[5];
    const float* W3  = (const float*)d_in[6];
    const float* b3  = (const float*)d_in[7];
    float*       out = (float*)d_out;

    __half* pW1 = (__half*)sym(g_W1);
    __half* pW2 = (__half*)sym(g_W2);
    __half* pW3 = (__half*)sym(g_W3);
    __half* A1  = (__half*)sym(g_A1);
    __half* A2  = (__half*)sym(g_A2);
    __half* A3  = (__half*)sym(g_A3);
    __half* h1h = (__half*)sym(g_h1h);
    __half* t3h = (__half*)sym(g_t3h);

    const int NB_N = (N_NODES + 255) / 256;

    const int SMEM_MMA = 2 * 2 * 128 * 72 * (int)sizeof(__half);  // 73728
    cudaFuncSetAttribute(k_mma<1, 256, true,  true >, cudaFuncAttributeMaxDynamicSharedMemorySize, SMEM_MMA);
    cudaFuncSetAttribute(k_mma<4, 256, true,  true >, cudaFuncAttributeMaxDynamicSharedMemorySize, SMEM_MMA);
    cudaFuncSetAttribute(k_mma<4, 128, false, false>, cudaFuncAttributeMaxDynamicSharedMemorySize, SMEM_MMA);

    // preprocessing: detect+init -> (degcount||prepx||prepw) -> alloc -> scatter
    k_front  <<<NB_N, 256>>>((const long long*)ei);
    k_mid    <<<NB_CONV + NB_PX + NB_PW, 256>>>(ei, x, W1, W2, W3);
    k_alloc  <<<NB_N, 256>>>();
    k_scatter<<<(N_EDGES / 4 + 255) / 256, 256>>>(ei);

    // Layer 1: agg(xh) -> A1; GEMM K=64 -> h1 fp16 (+b1, relu)
    k_agg1<<<(N_NODES * 32 + 255) / 256, 256>>>();
    {
        dim3 grid(2, M_TILES);               // N fast, M slow: A-tile L2 reuse
        k_mma<1, 256, true, true><<<grid, 256, SMEM_MMA>>>(A1, pW1, b1, h1h);
    }

    // Layer 2: agg(h1) single-pass -> A2; GEMM K=256 -> A3 fp16 (+b2, relu)
    k_agg2<<<(N_NODES * 32 + 255) / 256, 256>>>();
    {
        dim3 grid(2, M_TILES);
        k_mma<4, 256, true, true><<<grid, 256, SMEM_MMA>>>(A2, pW2, b2, A3);
    }

    // Layer 3: GEMM K=256 -> t3 fp16; agg(t3)+b3 -> out fp32
    {
        dim3 grid(1, M_TILES);
        k_mma<4, 128, false, false><<<grid, 256, SMEM_MMA>>>(A3, pW3, nullptr, t3h);
    }
    k_agg_out<<<(N_NODES * 32 + 255) / 256, 256>>>(out, b3);
}

// round 17
// speedup vs baseline: 1.0512x; 1.0254x over previous
#include <cuda_runtime.h>
#include <cuda_fp16.h>
#include <stdint.h>

#define N_NODES 100000
#define N_EDGES 1600000
#define IN_F 50
#define HID 256
#define OUT_F 121
#define M_TILES ((N_NODES + 127) / 128)   // 782

// ===================== scratch (static __device__) ==========================
__device__ int   g_flag;
__device__ int   g_total;
__device__ int   g_deg[N_NODES];
__device__ int   g_beg[N_NODES];
__device__ float g_dinv[N_NODES];
__device__ int   g_cur[N_NODES];
__device__ int   g_csr[N_EDGES];

__device__ __half g_W1[256 * 64];     // W1^T padded K->64  [n][k]
__device__ __half g_W2[256 * 256];    // W2^T
__device__ __half g_W3[128 * 256];    // W3^T padded N->128

__device__ __half g_A1[(size_t)N_NODES * 64];    // agg1 out (GEMM1 A)
__device__ __half g_A2[(size_t)N_NODES * 256];   // agg2 out (GEMM2 A)
__device__ __half g_xh [(size_t)N_NODES * 52];   // x fp16, padded 50->52
__device__ __half g_h1h[(size_t)N_NODES * 256];  // h1 fp16 (51.2MB: L2-resident)
__device__ __half g_t3h[(size_t)N_NODES * 128];  // t3 fp16 (25.6MB: L2-resident)

// ===================== small PTX helpers (baseline features only) ===========
__device__ __forceinline__ uint32_t smem_u32(const void* p) {
    uint32_t a;
    asm("{ .reg .u64 t; cvta.to.shared.u64 t, %1; cvt.u32.u64 %0, t; }" : "=r"(a) : "l"(p));
    return a;
}

#define CP_ASYNC16(dst_u32, src_ptr) \
    asm volatile("cp.async.cg.shared.global [%0], [%1], 16;" :: "r"(dst_u32), "l"(src_ptr))
#define CP_COMMIT() asm volatile("cp.async.commit_group;" ::: "memory")

#define LDM_X4(R, ADDR) \
    asm volatile("ldmatrix.sync.aligned.m8n8.x4.shared.b16 {%0,%1,%2,%3}, [%4];" \
        : "=r"((R)[0]), "=r"((R)[1]), "=r"((R)[2]), "=r"((R)[3]) : "r"(ADDR))

__device__ __forceinline__ void mma16816h(float* d, const uint32_t* a, const uint32_t* b) {
    asm volatile(
        "mma.sync.aligned.m16n8k16.row.col.f32.f16.f16.f32 "
        "{%0,%1,%2,%3}, {%4,%5,%6,%7}, {%8,%9}, {%0,%1,%2,%3};"
        : "+f"(d[0]), "+f"(d[1]), "+f"(d[2]), "+f"(d[3])
        : "r"(a[0]), "r"(a[1]), "r"(a[2]), "r"(a[3]), "r"(b[0]), "r"(b[1]));
}

// ===================== helpers: load 4 edge indices =========================
__device__ __forceinline__ void load4(const void* ei, size_t elem_off, int e4,
                                      int* v) {
    if (g_flag) {
        int4 a = ((const int4*)((const int*)ei + elem_off))[e4];
        v[0] = a.x; v[1] = a.y; v[2] = a.z; v[3] = a.w;
    } else {
        const longlong2* p = (const longlong2*)((const long long*)ei + elem_off);
        longlong2 a = p[e4 * 2], b = p[e4 * 2 + 1];
        v[0] = (int)a.x; v[1] = (int)a.y; v[2] = (int)b.x; v[3] = (int)b.y;
    }
}

// ===================== kernel 1: detect (block 0) + init (all blocks) =======
__global__ void k_front(const long long* __restrict__ ei64) {
    int v = blockIdx.x * blockDim.x + threadIdx.x;
    if (v < N_NODES) g_deg[v] = 1;
    if (blockIdx.x == 0) {
        __shared__ int bad;
        if (threadIdx.x == 0) { bad = 0; g_total = 0; }
        __syncthreads();
        int ok = 1;
        for (int i = threadIdx.x; i < 4096; i += 256) {
            long long t = ei64[i];
            if (t < 0 || t >= N_NODES) ok = 0;
        }
        if (!ok) atomicOr(&bad, 1);
        __syncthreads();
        if (threadIdx.x == 0) g_flag = bad;
    }
}

// ===================== kernel 2: degcount || prepx || prepw (block ranges) ==
#define NB_CONV ((N_EDGES / 4 + 255) / 256)            // 1563 (4 edges/thread)
#define NB_PX   ((N_NODES * 13 + 255) / 256)           // 5079 (2 half2/thread)
#define NB_PW   ((256*64 + 256*256 + 128*256 + 255) / 256)  // 480

__global__ void k_mid(const void* __restrict__ ei,
                      const float* __restrict__ x,
                      const float* __restrict__ W1, const float* __restrict__ W2,
                      const float* __restrict__ W3) {
    int b = blockIdx.x;
    if (b < NB_CONV) {
        int e4 = b * 256 + threadIdx.x;
        if (e4 * 4 >= N_EDGES) return;
        int c[4];
        load4(ei, N_EDGES, e4, c);
        #pragma unroll
        for (int q = 0; q < 4; q++) atomicAdd(&g_deg[c[q]], 1);
    } else if (b < NB_CONV + NB_PX) {
        int t = (b - NB_CONV) * 256 + threadIdx.x;
        if (t >= N_NODES * 13) return;
        int node = t / 13, cp = t - node * 13;
        __half2 v0, v1;
        int c0 = cp * 4;
        if (c0 + 1 < IN_F) {
            float2 f = *(const float2*)(x + (size_t)node * IN_F + c0);
            v0 = __floats2half2_rn(f.x, f.y);
        } else v0 = __floats2half2_rn(0.f, 0.f);
        if (c0 + 3 < IN_F) {
            float2 f = *(const float2*)(x + (size_t)node * IN_F + c0 + 2);
            v1 = __floats2half2_rn(f.x, f.y);
        } else if (c0 + 2 < IN_F) {
            v1 = __floats2half2_rn(x[(size_t)node * IN_F + c0 + 2], 0.f);
        } else v1 = __floats2half2_rn(0.f, 0.f);
        __half2* dst = (__half2*)(g_xh + (size_t)node * 52 + c0);
        dst[0] = v0;
        dst[1] = v1;
    } else {
        int i = (b - NB_CONV - NB_PX) * 256 + threadIdx.x;
        if (i < 256 * 64) {
            int n = i >> 6, k = i & 63;
            g_W1[i] = __float2half((k < IN_F) ? W1[(size_t)k * 256 + n] : 0.f);
        } else if (i < 256 * 64 + 256 * 256) {
            int j = i - 256 * 64;
            int n = j >> 8, k = j & 255;
            g_W2[j] = __float2half(W2[(size_t)k * 256 + n]);
        } else if (i < 256 * 64 + 256 * 256 + 128 * 256) {
            int j = i - 256 * 64 - 256 * 256;
            int n = j >> 8, k = j & 255;
            g_W3[j] = __float2half((n < OUT_F) ? W3[(size_t)k * OUT_F + n] : 0.f);
        }
    }
}

// ===================== CSR range allocation (no scan): warp-agg atomic ======
__global__ void k_alloc() {
    int v = blockIdx.x * blockDim.x + threadIdx.x;
    int lane = threadIdx.x & 31;
    int d = (v < N_NODES) ? g_deg[v] : 1;
    if (v < N_NODES) g_dinv[v] = rsqrtf((float)d);
    int cnt = (v < N_NODES) ? (d - 1) : 0;
    int pre = cnt;
    #pragma unroll
    for (int o = 1; o < 32; o <<= 1) {
        int t = __shfl_up_sync(0xFFFFFFFFu, pre, o);
        if (lane >= o) pre += t;
    }
    int total = __shfl_sync(0xFFFFFFFFu, pre, 31);
    int base = 0;
    if (lane == 31 && total > 0) base = atomicAdd(&g_total, total);
    base = __shfl_sync(0xFFFFFFFFu, base, 31);
    if (v < N_NODES) {
        int beg = base + pre - cnt;
        g_beg[v] = beg;
        g_cur[v] = beg;
    }
}

// ===================== scatter: 4 edges/thread, direct atomic slot ==========
__global__ void k_scatter(const void* __restrict__ ei) {
    int e4 = blockIdx.x * blockDim.x + threadIdx.x;
    if (e4 * 4 >= N_EDGES) return;
    int r[4], c[4];
    load4(ei, 0, e4, r);
    load4(ei, N_EDGES, e4, c);
    int p[4];
    #pragma unroll
    for (int q = 0; q < 4; q++) p[q] = atomicAdd(&g_cur[c[q]], 1);
    #pragma unroll
    for (int q = 0; q < 4; q++) g_csr[p[q]] = r[q];
}

// ===================== aggregation (fp16 gather + fp16 out) =================
__global__ void k_agg1() {
    const __half2* X2 = (const __half2*)g_xh;   // row stride 26
    int gw = (blockIdx.x * blockDim.x + threadIdx.x) >> 5;
    int lane = threadIdx.x & 31;
    if (gw >= N_NODES) return;
    int node = gw;
    bool act = lane < 25;
    int c2 = act ? lane : 0;
    float dv = g_dinv[node];
    float2 xv = __half22float2(X2[(size_t)node * 26 + c2]);
    float ax = dv * xv.x, ay = dv * xv.y;
    int beg = g_beg[node], end = beg + g_deg[node] - 1;
    int j = beg;
    for (; j + 4 <= end; j += 4) {
        int u0 = g_csr[j], u1 = g_csr[j + 1], u2 = g_csr[j + 2], u3 = g_csr[j + 3];
        float d0 = g_dinv[u0], d1 = g_dinv[u1], d2 = g_dinv[u2], d3 = g_dinv[u3];
        float2 a0 = __half22float2(X2[(size_t)u0 * 26 + c2]);
        float2 a1 = __half22float2(X2[(size_t)u1 * 26 + c2]);
        float2 a2 = __half22float2(X2[(size_t)u2 * 26 + c2]);
        float2 a3 = __half22float2(X2[(size_t)u3 * 26 + c2]);
        ax += d0 * a0.x; ay += d0 * a0.y;
        ax += d1 * a1.x; ay += d1 * a1.y;
        ax += d2 * a2.x; ay += d2 * a2.y;
        ax += d3 * a3.x; ay += d3 * a3.y;
    }
    for (; j < end; j++) {
        int u = g_csr[j];
        float d = g_dinv[u];
        float2 a = __half22float2(X2[(size_t)u * 26 + c2]);
        ax += d * a.x; ay += d * a.y;
    }
    float v0 = act ? dv * ax : 0.f;
    float v1 = act ? dv * ay : 0.f;
    *(__half2*)(g_A1 + (size_t)node * 64 + lane * 2) = __floats2half2_rn(v0, v1);
}

// layer-2 agg: single pass, uint4 lanes (8 halves), 32 lanes cover 256 cols.
__global__ void k_agg2() {
    const uint4* X = (const uint4*)g_h1h;       // row stride 32 uint4
    int gw = (blockIdx.x * blockDim.x + threadIdx.x) >> 5;
    int lane = threadIdx.x & 31;
    if (gw >= N_NODES) return;
    int node = gw;
    float dv = g_dinv[node];
    float a[8];
    {
        uint4 raw = X[(size_t)node * 32 + lane];
        float2 f0 = __half22float2(*(__half2*)&raw.x);
        float2 f1 = __half22float2(*(__half2*)&raw.y);
        float2 f2 = __half22float2(*(__half2*)&raw.z);
        float2 f3 = __half22float2(*(__half2*)&raw.w);
        a[0] = dv * f0.x; a[1] = dv * f0.y; a[2] = dv * f1.x; a[3] = dv * f1.y;
        a[4] = dv * f2.x; a[5] = dv * f2.y; a[6] = dv * f3.x; a[7] = dv * f3.y;
    }
    int beg = g_beg[node], end = beg + g_deg[node] - 1;
    int j = beg;
    for (; j + 4 <= end; j += 4) {
        int u0 = g_csr[j], u1 = g_csr[j + 1], u2 = g_csr[j + 2], u3 = g_csr[j + 3];
        float d0 = g_dinv[u0], d1 = g_dinv[u1], d2 = g_dinv[u2], d3 = g_dinv[u3];
        uint4 r0 = X[(size_t)u0 * 32 + lane];
        uint4 r1 = X[(size_t)u1 * 32 + lane];
        uint4 r2 = X[(size_t)u2 * 32 + lane];
        uint4 r3 = X[(size_t)u3 * 32 + lane];
        {
            float2 f0 = __half22float2(*(__half2*)&r0.x), f1 = __half22float2(*(__half2*)&r0.y);
            float2 f2 = __half22float2(*(__half2*)&r0.z), f3 = __half22float2(*(__half2*)&r0.w);
            a[0] += d0 * f0.x; a[1] += d0 * f0.y; a[2] += d0 * f1.x; a[3] += d0 * f1.y;
            a[4] += d0 * f2.x; a[5] += d0 * f2.y; a[6] += d0 * f3.x; a[7] += d0 * f3.y;
        }
        {
            float2 f0 = __half22float2(*(__half2*)&r1.x), f1 = __half22float2(*(__half2*)&r1.y);
            float2 f2 = __half22float2(*(__half2*)&r1.z), f3 = __half22float2(*(__half2*)&r1.w);
            a[0] += d1 * f0.x; a[1] += d1 * f0.y; a[2] += d1 * f1.x; a[3] += d1 * f1.y;
            a[4] += d1 * f2.x; a[5] += d1 * f2.y; a[6] += d1 * f3.x; a[7] += d1 * f3.y;
        }
        {
            float2 f0 = __half22float2(*(__half2*)&r2.x), f1 = __half22float2(*(__half2*)&r2.y);
            float2 f2 = __half22float2(*(__half2*)&r2.z), f3 = __half22float2(*(__half2*)&r2.w);
            a[0] += d2 * f0.x; a[1] += d2 * f0.y; a[2] += d2 * f1.x; a[3] += d2 * f1.y;
            a[4] += d2 * f2.x; a[5] += d2 * f2.y; a[6] += d2 * f3.x; a[7] += d2 * f3.y;
        }
        {
            float2 f0 = __half22float2(*(__half2*)&r3.x), f1 = __half22float2(*(__half2*)&r3.y);
            float2 f2 = __half22float2(*(__half2*)&r3.z), f3 = __half22float2(*(__half2*)&r3.w);
            a[0] += d3 * f0.x; a[1] += d3 * f0.y; a[2] += d3 * f1.x; a[3] += d3 * f1.y;
            a[4] += d3 * f2.x; a[5] += d3 * f2.y; a[6] += d3 * f3.x; a[7] += d3 * f3.y;
        }
    }
    for (; j < end; j++) {
        int u = g_csr[j];
        float d = g_dinv[u];
        uint4 r = X[(size_t)u * 32 + lane];
        float2 f0 = __half22float2(*(__half2*)&r.x), f1 = __half22float2(*(__half2*)&r.y);
        float2 f2 = __half22float2(*(__half2*)&r.z), f3 = __half22float2(*(__half2*)&r.w);
        a[0] += d * f0.x; a[1] += d * f0.y; a[2] += d * f1.x; a[3] += d * f1.y;
        a[4] += d * f2.x; a[5] += d * f2.y; a[6] += d * f3.x; a[7] += d * f3.y;
    }
    uint4 outv;
    *(__half2*)&outv.x = __floats2half2_rn(a[0] * dv, a[1] * dv);
    *(__half2*)&outv.y = __floats2half2_rn(a[2] * dv, a[3] * dv);
    *(__half2*)&outv.z = __floats2half2_rn(a[4] * dv, a[5] * dv);
    *(__half2*)&outv.w = __floats2half2_rn(a[6] * dv, a[7] * dv);
    *(uint4*)(g_A2 + (size_t)node * 256 + lane * 8) = outv;
}

// final agg: t3 fp16 [N][128] (uint2 lanes), +bias, out [N][121] fp32
__global__ void k_agg_out(float* __restrict__ OUT, const float* __restrict__ bias) {
    const uint2* X4 = (const uint2*)g_t3h;      // row stride 32 uint2
    int gw = (blockIdx.x * blockDim.x + threadIdx.x) >> 5;
    int lane = threadIdx.x & 31;
    if (gw >= N_NODES) return;
    int node = gw;
    float dv = g_dinv[node];
    uint2 raw = X4[(size_t)node * 32 + lane];
    float2 f01 = __half22float2(*(__half2*)&raw.x);
    float2 f23 = __half22float2(*(__half2*)&raw.y);
    float a0 = dv * f01.x, a1 = dv * f01.y, a2 = dv * f23.x, a3 = dv * f23.y;
    int beg = g_beg[node], end = beg + g_deg[node] - 1;
    int j = beg;
    for (; j + 4 <= end; j += 4) {
        int u0 = g_csr[j], u1 = g_csr[j + 1], u2 = g_csr[j + 2], u3 = g_csr[j + 3];
        float d0 = g_dinv[u0], d1 = g_dinv[u1], d2 = g_dinv[u2], d3 = g_dinv[u3];
        uint2 r0 = X4[(size_t)u0 * 32 + lane];
        uint2 r1 = X4[(size_t)u1 * 32 + lane];
        uint2 r2 = X4[(size_t)u2 * 32 + lane];
        uint2 r3 = X4[(size_t)u3 * 32 + lane];
        float2 p0a = __half22float2(*(__half2*)&r0.x), p0b = __half22float2(*(__half2*)&r0.y);
        float2 p1a = __half22float2(*(__half2*)&r1.x), p1b = __half22float2(*(__half2*)&r1.y);
        float2 p2a = __half22float2(*(__half2*)&r2.x), p2b = __half22float2(*(__half2*)&r2.y);
        float2 p3a = __half22float2(*(__half2*)&r3.x), p3b = __half22float2(*(__half2*)&r3.y);
        a0 += d0 * p0a.x; a1 += d0 * p0a.y; a2 += d0 * p0b.x; a3 += d0 * p0b.y;
        a0 += d1 * p1a.x; a1 += d1 * p1a.y; a2 += d1 * p1b.x; a3 += d1 * p1b.y;
        a0 += d2 * p2a.x; a1 += d2 * p2a.y; a2 += d2 * p2b.x; a3 += d2 * p2b.y;
        a0 += d3 * p3a.x; a1 += d3 * p3a.y; a2 += d3 * p3b.x; a3 += d3 * p3b.y;
    }
    for (; j < end; j++) {
        int u = g_csr[j];
        float d = g_dinv[u];
        uint2 r = X4[(size_t)u * 32 + lane];
        float2 pa = __half22float2(*(__half2*)&r.x), pb = __half22float2(*(__half2*)&r.y);
        a0 += d * pa.x; a1 += d * pa.y; a2 += d * pb.x; a3 += d * pb.y;
    }
    int c = lane * 4;
    float* dst = OUT + (size_t)node * OUT_F;
    if (c + 0 < OUT_F) dst[c + 0] = dv * a0 + bias[c + 0];
    if (c + 1 < OUT_F) dst[c + 1] = dv * a1 + bias[c + 1];
    if (c + 2 < OUT_F) dst[c + 2] = dv * a2 + bias[c + 2];
    if (c + 3 < OUT_F) dst[c + 3] = dv * a3 + bias[c + 3];
}

// ===================== layer-1 warp-MMA GEMM (fp16, BK=64) ==================
// Grid (NSPLIT, M_TILES): adjacent blocks share the A slab (L2 reuse).
template<int KT, int NNTOT, bool BIAS, bool RELU>
__global__ void __launch_bounds__(256, 2)
k_mma(const __half* __restrict__ A, const __half* __restrict__ B,
      const float* __restrict__ bias, __half* __restrict__ C) {
    constexpr int ASTR = KT * 64;
    constexpr int PAD = 72;
    constexpr int ST = 128 * PAD;
    extern __shared__ __half dsm[];

    const int tid = threadIdx.x;
    const int wid = tid >> 5, lane = tid & 31;
    const int wm = wid & 3, wn = wid >> 2;
    const int m0 = blockIdx.y * 128;
    const int n0 = blockIdx.x * 128;

    float acc[2][8][4];
    #pragma unroll
    for (int mt = 0; mt < 2; mt++)
        #pragma unroll
        for (int nt = 0; nt < 8; nt++)
            #pragma unroll
            for (int q = 0; q < 4; q++) acc[mt][nt][q] = 0.f;

    auto stage = [&](int s, int c) {
        __half* base = dsm + s * 2 * ST;
        #pragma unroll
        for (int it = 0; it < 4; it++) {
            int idx = it * 256 + tid;
            int row = idx >> 3, chk = idx & 7;
            int m = m0 + row; if (m >= N_NODES) m = N_NODES - 1;
            size_t goA = (size_t)m * ASTR + c * 64 + chk * 8;
            size_t goB = (size_t)(n0 + row) * ASTR + c * 64 + chk * 8;
            int so = row * PAD + chk * 8;
            CP_ASYNC16(smem_u32(base + so), A + goA);
            CP_ASYNC16(smem_u32(base + ST + so), B + goB);
        }
        CP_COMMIT();
    };

    stage(0, 0);
    for (int c = 0; c < KT; c++) {
        if (c + 1 < KT) {
            stage((c + 1) & 1, c + 1);
            asm volatile("cp.async.wait_group 1;" ::: "memory");
        } else {
            asm volatile("cp.async.wait_group 0;" ::: "memory");
        }
        __syncthreads();

        const __half* sA = dsm + (c & 1) * 2 * ST;
        const __half* sB = sA + ST;

        #pragma unroll
        for (int ks = 0; ks < 4; ks++) {
            const int kc = ks * 16;
            uint32_t a_f[2][4];
            #pragma unroll
            for (int mt = 0; mt < 2; mt++) {
                int r = wm * 32 + mt * 16 + (lane & 15);
                int cA = kc + ((lane >> 4) << 3);
                LDM_X4(a_f[mt], smem_u32(sA + r * PAD + cA));
            }
            #pragma unroll
            for (int ntp = 0; ntp < 4; ntp++) {
                int br = wn * 64 + ntp * 16 + (lane & 7) + ((lane & 16) ? 8 : 0);
                int cB = kc + ((lane & 8) ? 8 : 0);
                uint32_t b_f[4];
                LDM_X4(b_f, smem_u32(sB + br * PAD + cB));
                #pragma unroll
                for (int half = 0; half < 2; half++) {
                    int nt = ntp * 2 + half;
                    #pragma unroll
                    for (int mt = 0; mt < 2; mt++)
                        mma16816h(acc[mt][nt], a_f[mt], b_f + 2 * half);
                }
            }
        }
        __syncthreads();
    }

    #pragma unroll
    for (int mt = 0; mt < 2; mt++) {
        int mrow = m0 + wm * 32 + mt * 16 + (lane >> 2);
        #pragma unroll
        for (int nt = 0; nt < 8; nt++) {
            int n = n0 + wn * 64 + nt * 8 + (lane & 3) * 2;
            float v0 = acc[mt][nt][0], v1 = acc[mt][nt][1];
            float v2 = acc[mt][nt][2], v3 = acc[mt][nt][3];
            if (BIAS) {
                float bb0 = bias[n], bb1 = bias[n + 1];
                v0 += bb0; v1 += bb1; v2 += bb0; v3 += bb1;
            }
            if (RELU) {
                v0 = fmaxf(v0, 0.f); v1 = fmaxf(v1, 0.f);
                v2 = fmaxf(v2, 0.f); v3 = fmaxf(v3, 0.f);
            }
            if (mrow < N_NODES)
                *(__half2*)(C + (size_t)mrow * NNTOT + n) = __floats2half2_rn(v0, v1);
            if (mrow + 8 < N_NODES)
                *(__half2*)(C + (size_t)(mrow + 8) * NNTOT + n) = __floats2half2_rn(v2, v3);
        }
    }
}

// ===================== FUSED layers 2+3: t3 = relu(A2@W2+b2) @ W3 ===========
// One CTA = 128 rows. Phase 1: 128x256 = A2[128,256] @ W2[256,256]^T (full N).
// Phase 2: relu+bias -> fp16 tile P in smem -> t3[128,128] = P @ W3[128,256]^T.
// smem: staging 2 stages x (A 128x72 + B 256x72) = 55296 halves = 110592 B.
//       phase 2 overlays: P[128][264] at 0, W3 double-buffer at 33792.
__global__ void __launch_bounds__(256, 1)
k_mma23(const __half* __restrict__ A, const __half* __restrict__ B2,
        const float* __restrict__ bias2, const __half* __restrict__ B3,
        __half* __restrict__ C) {
    constexpr int PAD = 72;
    constexpr int STA = 128 * PAD;           // 9216
    constexpr int STB = 256 * PAD;           // 18432
    constexpr int STG = STA + STB;           // per stage
    constexpr int PADP = 264;                // P row stride (halves)
    constexpr int W3OFF = 128 * PADP;        // 33792: W3 staging base
    extern __shared__ __half dsm[];

    const int tid = threadIdx.x;
    const int wid = tid >> 5, lane = tid & 31;
    const int wm = wid & 3, wn = wid >> 2;   // phase1: 4 M-quads x 2 N-halves(128)
    const int m0 = blockIdx.x * 128;

    // ---------------- phase 1: acc1[2][16][4] = 128x256 / 8 warps ----------
    float acc1[2][16][4];
    #pragma unroll
    for (int mt = 0; mt < 2; mt++)
        #pragma unroll
        for (int nt = 0; nt < 16; nt++)
            #pragma unroll
            for (int q = 0; q < 4; q++) acc1[mt][nt][q] = 0.f;

    auto stage1 = [&](int s, int c) {
        __half* base = dsm + s * STG;
        #pragma unroll
        for (int it = 0; it < 4; it++) {     // A: 128 rows x 8 chunks
            int idx = it * 256 + tid;
            int row = idx >> 3, chk = idx & 7;
            int m = m0 + row; if (m >= N_NODES) m = N_NODES - 1;
            CP_ASYNC16(smem_u32(base + row * PAD + chk * 8),
                       A + (size_t)m * 256 + c * 64 + chk * 8);
        }
        #pragma unroll
        for (int it = 0; it < 8; it++) {     // B: 256 rows x 8 chunks
            int idx = it * 256 + tid;
            int row = idx >> 3, chk = idx & 7;
            CP_ASYNC16(smem_u32(base + STA + row * PAD + chk * 8),
                       B2 + (size_t)row * 256 + c * 64 + chk * 8);
        }
        CP_COMMIT();
    };

    stage1(0, 0);
    for (int c = 0; c < 4; c++) {
        if (c + 1 < 4) {
            stage1((c + 1) & 1, c + 1);
            asm volatile("cp.async.wait_group 1;" ::: "memory");
        } else {
            asm volatile("cp.async.wait_group 0;" ::: "memory");
        }
        __syncthreads();
        const __half* sA = dsm + (c & 1) * STG;
        const __half* sB = sA + STA;
        #pragma unroll
        for (int ks = 0; ks < 4; ks++) {
            const int kc = ks * 16;
            uint32_t a_f[2][4];
            #pragma unroll
            for (int mt = 0; mt < 2; mt++) {
                int r = wm * 32 + mt * 16 + (lane & 15);
                int cA = kc + ((lane >> 4) << 3);
                LDM_X4(a_f[mt], smem_u32(sA + r * PAD + cA));
            }
            #pragma unroll
            for (int ntp = 0; ntp < 8; ntp++) {
                int br = wn * 128 + ntp * 16 + (lane & 7) + ((lane & 16) ? 8 : 0);
                int cB = kc + ((lane & 8) ? 8 : 0);
                uint32_t b_f[4];
                LDM_X4(b_f, smem_u32(sB + br * PAD + cB));
                #pragma unroll
                for (int half = 0; half < 2; half++) {
                    int nt = ntp * 2 + half;
                    #pragma unroll
                    for (int mt = 0; mt < 2; mt++)
                        mma16816h(acc1[mt][nt], a_f[mt], b_f + 2 * half);
                }
            }
        }
        __syncthreads();
    }

    // ---------------- phase 2a: bias+relu -> P tile (fp16) -----------------
    #pragma unroll
    for (int mt = 0; mt < 2; mt++) {
        int r = wm * 32 + mt * 16 + (lane >> 2);
        #pragma unroll
        for (int nt = 0; nt < 16; nt++) {
            int n = wn * 128 + nt * 8 + (lane & 3) * 2;
            float bb0 = bias2[n], bb1 = bias2[n + 1];
            float v0 = fmaxf(acc1[mt][nt][0] + bb0, 0.f);
            float v1 = fmaxf(acc1[mt][nt][1] + bb1, 0.f);
            float v2 = fmaxf(acc1[mt][nt][2] + bb0, 0.f);
            float v3 = fmaxf(acc1[mt][nt][3] + bb1, 0.f);
            *(__half2*)(dsm + r * PADP + n) = __floats2half2_rn(v0, v1);
            *(__half2*)(dsm + (r + 8) * PADP + n) = __floats2half2_rn(v2, v3);
        }
    }
    __syncthreads();

    // ---------------- phase 2b: t3 = P @ W3^T ------------------------------
    float acc2[2][8][4];
    #pragma unroll
    for (int mt = 0; mt < 2; mt++)
        #pragma unroll
        for (int nt = 0; nt < 8; nt++)
            #pragma unroll
            for (int q = 0; q < 4; q++) acc2[mt][nt][q] = 0.f;

    auto stage2 = [&](int s, int c) {        // W3 chunk: 128 rows x 64 cols
        __half* base = dsm + W3OFF + s * STA;
        #pragma unroll
        for (int it = 0; it < 4; it++) {
            int idx = it * 256 + tid;
            int row = idx >> 3, chk = idx & 7;
            CP_ASYNC16(smem_u32(base + row * PAD + chk * 8),
                       B3 + (size_t)row * 256 + c * 64 + chk * 8);
        }
        CP_COMMIT();
    };

    stage2(0, 0);
    for (int c = 0; c < 4; c++) {
        if (c + 1 < 4) {
            stage2((c + 1) & 1, c + 1);
            asm volatile("cp.async.wait_group 1;" ::: "memory");
        } else {
            asm volatile("cp.async.wait_group 0;" ::: "memory");
        }
        __syncthreads();
        const __half* sW = dsm + W3OFF + (c & 1) * STA;
        #pragma unroll
        for (int ks = 0; ks < 4; ks++) {
            uint32_t a_f[2][4];
            #pragma unroll
            for (int mt = 0; mt < 2; mt++) {
                int r = wm * 32 + mt * 16 + (lane & 15);
                int cA = c * 64 + ks * 16 + ((lane >> 4) << 3);
                LDM_X4(a_f[mt], smem_u32(dsm + r * PADP + cA));
            }
            #pragma unroll
            for (int ntp = 0; ntp < 4; ntp++) {
                int br = wn * 64 + ntp * 16 + (lane & 7) + ((lane & 16) ? 8 : 0);
                int cB = ks * 16 + ((lane & 8) ? 8 : 0);
                uint32_t b_f[4];
                LDM_X4(b_f, smem_u32(sW + br * PAD + cB));
                #pragma unroll
                for (int half = 0; half < 2; half++) {
                    int nt = ntp * 2 + half;
                    #pragma unroll
                    for (int mt = 0; mt < 2; mt++)
                        mma16816h(acc2[mt][nt], a_f[mt], b_f + 2 * half);
                }
            }
        }
        __syncthreads();
    }

    // epilogue: write t3h [node][128]
    #pragma unroll
    for (int mt = 0; mt < 2; mt++) {
        int mrow = m0 + wm * 32 + mt * 16 + (lane >> 2);
        #pragma unroll
        for (int nt = 0; nt < 8; nt++) {
            int n = wn * 64 + nt * 8 + (lane & 3) * 2;
            if (mrow < N_NODES)
                *(__half2*)(C + (size_t)mrow * 128 + n) =
                    __floats2half2_rn(acc2[mt][nt][0], acc2[mt][nt][1]);
            if (mrow + 8 < N_NODES)
                *(__half2*)(C + (size_t)(mrow + 8) * 128 + n) =
                    __floats2half2_rn(acc2[mt][nt][2], acc2[mt][nt][3]);
        }
    }
}

// ===================== launch ===============================================
static inline void* sym(const void* s) {
    void* p = nullptr;
    cudaGetSymbolAddress(&p, s);
    return p;
}

extern "C" void kernel_launch(void* const* d_in, const int* in_sizes, int n_in,
                              void* d_out, int out_size) {
    const float* x   = (const float*)d_in[0];
    const void*  ei  = d_in[1];
    const float* W1  = (const float*)d_in[2];
    const float* b1  = (const float*)d_in[3];
    const float* W2  = (const float*)d_in[4];
    const float* b2  = (const float*)d_in[5];
    const float* W3  = (const float*)d_in[6];
    const float* b3  = (const float*)d_in[7];
    float*       out = (float*)d_out;

    __half* pW1 = (__half*)sym(g_W1);
    __half* pW2 = (__half*)sym(g_W2);
    __half* pW3 = (__half*)sym(g_W3);
    __half* A1  = (__half*)sym(g_A1);
    __half* A2  = (__half*)sym(g_A2);
    __half* h1h = (__half*)sym(g_h1h);
    __half* t3h = (__half*)sym(g_t3h);

    const int NB_N = (N_NODES + 255) / 256;

    const int SMEM_MMA  = 2 * 2 * 128 * 72 * (int)sizeof(__half);          // 73728
    const int SMEM_F    = 2 * (128 * 72 + 256 * 72) * (int)sizeof(__half); // 110592
    cudaFuncSetAttribute(k_mma<1, 256, true, true>, cudaFuncAttributeMaxDynamicSharedMemorySize, SMEM_MMA);
    cudaFuncSetAttribute(k_mma23, cudaFuncAttributeMaxDynamicSharedMemorySize, SMEM_F);

    // preprocessing: detect+init -> (degcount||prepx||prepw) -> alloc -> scatter
    k_front  <<<NB_N, 256>>>((const long long*)ei);
    k_mid    <<<NB_CONV + NB_PX + NB_PW, 256>>>(ei, x, W1, W2, W3);
    k_alloc  <<<NB_N, 256>>>();
    k_scatter<<<(N_EDGES / 4 + 255) / 256, 256>>>(ei);

    // Layer 1: agg(xh) -> A1; GEMM K=64 -> h1 fp16 (+b1, relu)
    k_agg1<<<(N_NODES * 32 + 255) / 256, 256>>>();
    {
        dim3 grid(2, M_TILES);
        k_mma<1, 256, true, true><<<grid, 256, SMEM_MMA>>>(A1, pW1, b1, h1h);
    }

    // Layer 2+3 fused: agg(h1) -> A2; t3 = relu(A2@W2+b2)@W3 -> t3h
    k_agg2<<<(N_NODES * 32 + 255) / 256, 256>>>();
    k_mma23<<<M_TILES, 256, SMEM_F>>>(A2, pW2, b2, pW3, t3h);

    // final aggregation (+b3) -> out
    k_agg_out<<<(N_NODES * 32 + 255) / 256, 256>>>(out, b3);
}